// round 7
// baseline (speedup 1.0000x reference)
#include <cuda_runtime.h>
#include <cuda_bf16.h>
#include <cstdint>
#include <math.h>

#define MM 2048
#define DD 7686
#define HH 512
#define OO 8
#define NN 8206
#define KP 7744            // 121 * 64
#define WROWS 7744
#define KC2 (KP / 64)      // 121
#define INV254 (1.0f / 254.0f)

__device__ __forceinline__ uint32_t smem_to_u32(const void* p) {
    uint32_t a;
    asm("{ .reg .u64 t; cvta.to.shared.u64 t, %1; cvt.u32.u64 %0, t; }"
        : "=r"(a) : "l"(p));
    return a;
}
__device__ __forceinline__ void cpa16(uint32_t s, const void* g) {
    asm volatile("cp.async.cg.shared.global [%0], [%1], 16;" :: "r"(s), "l"(g) : "memory");
}
#define CP_COMMIT() asm volatile("cp.async.commit_group;" ::: "memory")

__device__ __forceinline__ void ldsm4(uint32_t (&r)[4], uint32_t addr) {
    asm volatile("ldmatrix.sync.aligned.m8n8.x4.shared.b16 {%0,%1,%2,%3}, [%4];"
                 : "=r"(r[0]), "=r"(r[1]), "=r"(r[2]), "=r"(r[3]) : "r"(addr));
}
__device__ __forceinline__ void mma8(int (&d)[4], const uint32_t (&a)[4],
                                     uint32_t b0, uint32_t b1) {
    asm volatile(
        "mma.sync.aligned.m16n8k32.row.col.s32.s8.s8.s32 "
        "{%0,%1,%2,%3}, {%4,%5,%6,%7}, {%8,%9}, {%0,%1,%2,%3};"
        : "+r"(d[0]), "+r"(d[1]), "+r"(d[2]), "+r"(d[3])
        : "r"(a[0]), "r"(a[1]), "r"(a[2]), "r"(a[3]), "r"(b0), "r"(b1));
}
__device__ __forceinline__ uint32_t sw_off(int row, int c) {
    uint32_t o = (uint32_t)(row * 64 + c * 16);
    return o ^ ((o >> 3) & 0x30);
}

// ---------------- device scratch ----------------
__device__ int8_t g_xq0[(size_t)MM * KP];
__device__ int8_t g_xq1[(size_t)MM * KP];
__device__ int8_t g_wt0[(size_t)WROWS * KP];
__device__ int8_t g_wt1[(size_t)WROWS * KP];
__device__ int8_t g_qq0[(size_t)MM * KP];
__device__ int8_t g_qq1[(size_t)MM * KP];
__device__ int8_t g_kq0[(size_t)MM * KP];
__device__ int8_t g_kq1[(size_t)MM * KP];
__device__ float g_sX[MM];
__device__ float g_sW[WROWS];
__device__ float g_sQ[MM];
__device__ float g_sK[MM];
__device__ float g_wmax_part[16 * WROWS];
__device__ float g_q[(size_t)MM * DD];
__device__ float g_k[(size_t)MM * DD];
__device__ float g_scores[(size_t)MM * MM];
__device__ float g_cs_part[16 * MM];
__device__ float g_colsum[MM];
__device__ float g_part[16 * DD];
__device__ float g_u[DD];
__device__ float g_context[DD];
__device__ float g_s1_part[61 * (HH + OO)];
__device__ float g_vals1[HH + OO];
__device__ float g_s2_part[32 * OO];

// ---------------- per-row 2-slice int8 quantization ----------------
__global__ void quant_rows(const float* __restrict__ x, int cols,
                           int8_t* __restrict__ o0, int8_t* __restrict__ o1,
                           float* __restrict__ sArr)
{
    const int r = blockIdx.x;
    const int t = threadIdx.x;
    const float* xr = x + (size_t)r * cols;

    float mx = 0.f;
    for (int c = t; c < cols; c += 256) mx = fmaxf(mx, fabsf(xr[c]));
    __shared__ float sh[32];
    #pragma unroll
    for (int o = 16; o > 0; o >>= 1) mx = fmaxf(mx, __shfl_xor_sync(0xffffffff, mx, o));
    if ((t & 31) == 0) sh[t >> 5] = mx;
    __syncthreads();
    if (t < 32) {
        float m = (t < 8) ? sh[t] : 0.f;
        #pragma unroll
        for (int o = 4; o > 0; o >>= 1) m = fmaxf(m, __shfl_xor_sync(0xffffffff, m, o));
        sh[0] = m;
    }
    __syncthreads();
    const float mc = fmaxf(sh[0], 1e-20f);
    if (t == 0) sArr[r] = mc * (1.0f / 127.0f);
    const float inv = 127.0f / mc;

    for (int c4 = t * 4; c4 < KP; c4 += 1024) {
        char v0[4], v1[4];
        #pragma unroll
        for (int j = 0; j < 4; ++j) {
            int col = c4 + j;
            float v = (col < cols) ? xr[col] : 0.f;
            float tq = v * inv;
            float r0 = rintf(tq);
            v0[j] = (char)(int)r0;
            v1[j] = (char)(int)rintf((tq - r0) * 254.0f);
        }
        *(char4*)(o0 + (size_t)r * KP + c4) = make_char4(v0[0], v0[1], v0[2], v0[3]);
        *(char4*)(o1 + (size_t)r * KP + c4) = make_char4(v1[0], v1[1], v1[2], v1[3]);
    }
}

// ---------------- column-max |W|, partial + reduce ----------------
__global__ void wmax_part(const float* __restrict__ W)
{
    int c = blockIdx.x * 256 + threadIdx.x;
    if (c >= WROWS) return;
    int k0 = blockIdx.y * 481;
    float mx = 0.f;
    if (c < DD)
        for (int i = 0; i < 481; ++i) {
            int k = k0 + i;
            if (k < DD) mx = fmaxf(mx, fabsf(W[(size_t)k * DD + c]));
        }
    g_wmax_part[blockIdx.y * WROWS + c] = mx;
}
__global__ void wmax_red()
{
    int c = blockIdx.x * 256 + threadIdx.x;
    if (c >= WROWS) return;
    float mx = 0.f;
    #pragma unroll
    for (int y = 0; y < 16; ++y) mx = fmaxf(mx, g_wmax_part[y * WROWS + c]);
    g_sW[c] = fmaxf(mx, 1e-20f) * (1.0f / 127.0f);
}

// ---------------- transpose + 2-slice quantize W -> Wt[n][k] --------------------
// grid (WROWS/64, KP/32), block 256.
__global__ void quantT_w(const float* __restrict__ W,
                         int8_t* __restrict__ T0, int8_t* __restrict__ T1)
{
    __shared__ float sT[32][65];
    const int t = threadIdx.x;
    const int n0 = blockIdx.x * 64;
    const int k0 = blockIdx.y * 32;

    #pragma unroll
    for (int i = 0; i < 8; ++i) {
        int idx = i * 256 + t;
        int kl = idx >> 6, nl = idx & 63;
        int k = k0 + kl, n = n0 + nl;
        sT[kl][nl] = (k < DD && n < DD) ? W[(size_t)k * DD + n] : 0.f;
    }
    __syncthreads();

    const int nl = t >> 2;
    const int kg = (t & 3) * 8;
    const int n = n0 + nl;
    const float inv = 1.0f / g_sW[n];
    char b0[8], b1[8];
    #pragma unroll
    for (int j = 0; j < 8; ++j) {
        float v = sT[kg + j][nl];
        float tq = v * inv;
        float r0 = rintf(tq);
        b0[j] = (char)(int)r0;
        b1[j] = (char)(int)rintf((tq - r0) * 254.0f);
    }
    size_t off = (size_t)n * KP + k0 + kg;
    *(char4*)(T0 + off)     = make_char4(b0[0], b0[1], b0[2], b0[3]);
    *(char4*)(T0 + off + 4) = make_char4(b0[4], b0[5], b0[6], b0[7]);
    *(char4*)(T1 + off)     = make_char4(b1[0], b1[1], b1[2], b1[3]);
    *(char4*)(T1 + off + 4) = make_char4(b1[4], b1[5], b1[6], b1[7]);
}

// ---------------- int8 2-slice GEMM: CTA 128x64, 4 warps (64x32) ----------------
// C[m,n] = scale * sA[m]*sB[n]*(acc0 + acc1/254) (+ bias[n])
#define S8_A0 0
#define S8_A1 8192
#define S8_B0 16384
#define S8_B1 20480
#define STAGE8 24576
#define SMEM8 (3 * STAGE8)

__global__ __launch_bounds__(128, 2)
void tc_gemm8(const int8_t* __restrict__ A0, const int8_t* __restrict__ A1,
              const int8_t* __restrict__ B0, const int8_t* __restrict__ B1,
              const float* __restrict__ sA, const float* __restrict__ sB,
              const float* __restrict__ bias, float scale,
              float* __restrict__ C, int Cld)
{
    extern __shared__ char smem[];
    const uint32_t sb = smem_to_u32(smem);
    const int t = threadIdx.x, wid = t >> 5, lid = t & 31;
    const int m0 = blockIdx.y * 128, n0 = blockIdx.x * 64;
    const int rl = t >> 2, cl = t & 3;
    const uint32_t soR[4] = { sw_off(rl, cl), sw_off(rl + 32, cl),
                              sw_off(rl + 64, cl), sw_off(rl + 96, cl) };

    int acc0[4][4][4], acc1[4][4][4];
    #pragma unroll
    for (int a = 0; a < 4; ++a)
        #pragma unroll
        for (int b = 0; b < 4; ++b)
            #pragma unroll
            for (int c = 0; c < 4; ++c) { acc0[a][b][c] = 0; acc1[a][b][c] = 0; }

    auto load_stage = [&](int kc, int slot) {
        const int k0 = kc * 64;
        const uint32_t st = sb + slot * STAGE8;
        #pragma unroll
        for (int i = 0; i < 4; ++i) {
            size_t ga = (size_t)(m0 + rl + 32 * i) * KP + k0 + cl * 16;
            cpa16(st + S8_A0 + soR[i], A0 + ga);
            cpa16(st + S8_A1 + soR[i], A1 + ga);
        }
        #pragma unroll
        for (int i = 0; i < 2; ++i) {
            size_t gb = (size_t)(n0 + rl + 32 * i) * KP + k0 + cl * 16;
            cpa16(st + S8_B0 + soR[i], B0 + gb);
            cpa16(st + S8_B1 + soR[i], B1 + gb);
        }
        CP_COMMIT();
    };

    const int wm = wid >> 1, wn = wid & 1;
    const int lrow = lid & 15, lcg = lid >> 4;

    load_stage(0, 0);
    load_stage(1, 1);

    int slot = 0, nslot = 2;
    for (int kc = 0; kc < KC2; ++kc) {
        asm volatile("cp.async.wait_group 1;" ::: "memory");
        __syncthreads();
        if (kc + 2 < KC2) load_stage(kc + 2, nslot);
        else CP_COMMIT();

        const uint32_t st = sb + slot * STAGE8;
        slot = (slot == 2) ? 0 : slot + 1;
        nslot = (nslot == 2) ? 0 : nslot + 1;

        #pragma unroll
        for (int ks = 0; ks < 2; ++ks) {
            const int ccol = ks * 2 + lcg;
            uint32_t a0f[4][4], a1f[4][4];
            #pragma unroll
            for (int mt = 0; mt < 4; ++mt) {
                uint32_t so = sw_off(wm * 64 + mt * 16 + lrow, ccol);
                ldsm4(a0f[mt], st + S8_A0 + so);
                ldsm4(a1f[mt], st + S8_A1 + so);
            }
            uint32_t b0f[4][2], b1f[4][2];
            #pragma unroll
            for (int p = 0; p < 2; ++p) {
                uint32_t so = sw_off(wn * 32 + p * 16 + lrow, ccol);
                uint32_t r[4];
                ldsm4(r, st + S8_B0 + so);
                b0f[2*p][0] = r[0]; b0f[2*p][1] = r[2];
                b0f[2*p+1][0] = r[1]; b0f[2*p+1][1] = r[3];
                ldsm4(r, st + S8_B1 + so);
                b1f[2*p][0] = r[0]; b1f[2*p][1] = r[2];
                b1f[2*p+1][0] = r[1]; b1f[2*p+1][1] = r[3];
            }
            #pragma unroll
            for (int mt = 0; mt < 4; ++mt)
                #pragma unroll
                for (int q = 0; q < 4; ++q) {
                    mma8(acc0[mt][q], a0f[mt], b0f[q][0], b0f[q][1]);
                    mma8(acc1[mt][q], a0f[mt], b1f[q][0], b1f[q][1]);
                    mma8(acc1[mt][q], a1f[mt], b0f[q][0], b0f[q][1]);
                }
        }
    }

    const int g = lid >> 2, t4 = lid & 3;
    #pragma unroll
    for (int mt = 0; mt < 4; ++mt) {
        #pragma unroll
        for (int nt = 0; nt < 4; ++nt) {
            const int m = m0 + wm * 64 + mt * 16 + g;
            const int n = n0 + wn * 32 + nt * 8 + t4 * 2;
            if (n + 1 >= Cld && n >= Cld) continue;
            const float sa0 = __ldg(sA + m) * scale;
            const float sa1 = __ldg(sA + m + 8) * scale;
            const float sb0 = __ldg(sB + n);
            const float sb1 = __ldg(sB + n + 1);
            float bb0 = bias ? __ldg(bias + n) : 0.f;
            float bb1 = bias ? __ldg(bias + n + 1) : 0.f;
            float v0 = sa0 * sb0 * ((float)acc0[mt][nt][0] + (float)acc1[mt][nt][0] * INV254) + bb0;
            float v1 = sa0 * sb1 * ((float)acc0[mt][nt][1] + (float)acc1[mt][nt][1] * INV254) + bb1;
            float v2 = sa1 * sb0 * ((float)acc0[mt][nt][2] + (float)acc1[mt][nt][2] * INV254) + bb0;
            float v3 = sa1 * sb1 * ((float)acc0[mt][nt][3] + (float)acc1[mt][nt][3] * INV254) + bb1;
            if (n + 1 < Cld) {
                *(float2*)(C + (size_t)m * Cld + n) = make_float2(v0, v1);
                *(float2*)(C + (size_t)(m + 8) * Cld + n) = make_float2(v2, v3);
            } else {
                C[(size_t)m * Cld + n] = v0;
                C[(size_t)(m + 8) * Cld + n] = v2;
            }
        }
    }
}

// ---------------- softmax / reductions / sweeps (unchanged) ----------------
__global__ void softmax_rows(float* __restrict__ S)
{
    const int row = blockIdx.x;
    const int t = threadIdx.x;
    float* r = S + (size_t)row * MM;
    float v[8];
    #pragma unroll
    for (int i = 0; i < 8; ++i) v[i] = r[i * 256 + t];
    float mx = v[0];
    #pragma unroll
    for (int i = 1; i < 8; ++i) mx = fmaxf(mx, v[i]);
    __shared__ float sh[32];
    #pragma unroll
    for (int o = 16; o > 0; o >>= 1) mx = fmaxf(mx, __shfl_xor_sync(0xffffffff, mx, o));
    if ((t & 31) == 0) sh[t >> 5] = mx;
    __syncthreads();
    if (t < 32) {
        float m = (t < 8) ? sh[t] : -INFINITY;
        #pragma unroll
        for (int o = 4; o > 0; o >>= 1) m = fmaxf(m, __shfl_xor_sync(0xffffffff, m, o));
        sh[0] = m;
    }
    __syncthreads();
    mx = sh[0];
    __syncthreads();
    float sum = 0.f;
    #pragma unroll
    for (int i = 0; i < 8; ++i) { v[i] = expf(v[i] - mx); sum += v[i]; }
    #pragma unroll
    for (int o = 16; o > 0; o >>= 1) sum += __shfl_xor_sync(0xffffffff, sum, o);
    if ((t & 31) == 0) sh[t >> 5] = sum;
    __syncthreads();
    if (t < 32) {
        float s = (t < 8) ? sh[t] : 0.f;
        #pragma unroll
        for (int o = 4; o > 0; o >>= 1) s += __shfl_xor_sync(0xffffffff, s, o);
        sh[0] = s;
    }
    __syncthreads();
    float inv = 1.f / sh[0];
    #pragma unroll
    for (int i = 0; i < 8; ++i) r[i * 256 + t] = v[i] * inv;
}

__global__ void colsum_part(const float* __restrict__ P)
{
    int j = blockIdx.x * 256 + threadIdx.x;
    int r0 = blockIdx.y * 128;
    float acc = 0.f;
    for (int r = 0; r < 128; ++r) acc += P[(size_t)(r0 + r) * MM + j];
    g_cs_part[blockIdx.y * MM + j] = acc;
}
__global__ void colsum_reduce()
{
    int j = blockIdx.x * 256 + threadIdx.x;
    float acc = 0.f;
    #pragma unroll
    for (int c = 0; c < 16; ++c) acc += g_cs_part[c * MM + j];
    g_colsum[j] = acc;
}
__global__ void u_part(const float* __restrict__ X)
{
    int j = blockIdx.x * 256 + threadIdx.x;
    if (j >= DD) return;
    int r0 = blockIdx.y * 128;
    float acc = 0.f;
    for (int r = 0; r < 128; ++r) {
        int l = r0 + r;
        acc += g_colsum[l] * X[(size_t)l * DD + j];
    }
    g_part[blockIdx.y * DD + j] = acc;
}
__global__ void u_reduce()
{
    int j = blockIdx.x * 256 + threadIdx.x;
    if (j >= DD) return;
    float acc = 0.f;
    #pragma unroll
    for (int c = 0; c < 16; ++c) acc += g_part[c * DD + j];
    g_u[j] = acc * (1.0f / (float)MM);
}
__global__ void ctx2_part(const float* __restrict__ Wv)
{
    int j = blockIdx.x * 256 + threadIdx.x;
    if (j >= DD) return;
    int i0 = blockIdx.y * 481;
    float acc = 0.f;
    for (int r = 0; r < 481; ++r) {
        int i = i0 + r;
        if (i < DD) acc += g_u[i] * Wv[(size_t)i * DD + j];
    }
    g_part[blockIdx.y * DD + j] = acc;
}
__global__ void ctx2_reduce(const float* __restrict__ bv)
{
    int j = blockIdx.x * 256 + threadIdx.x;
    if (j >= DD) return;
    float acc = 0.f;
    #pragma unroll
    for (int c = 0; c < 16; ++c) acc += g_part[c * DD + j];
    g_context[j] = acc + bv[j];
}
__global__ void sweep1_part(const float* __restrict__ mu, const float* __restrict__ sig,
                            const float* __restrict__ eps)
{
    int jj = blockIdx.x * 256 + threadIdx.x;
    if (jj >= HH + OO) return;
    int j = DD + jj;
    int i0 = blockIdx.y * 126;
    float acc = 0.f;
    for (int r = 0; r < 126; ++r) {
        int i = i0 + r;
        size_t off = (size_t)i * NN + j;
        acc += g_context[i] * (mu[off] + sig[off] * eps[off]);
    }
    g_s1_part[blockIdx.y * (HH + OO) + jj] = acc;
}
__global__ void sweep1_final(const float* __restrict__ bmu, const float* __restrict__ bsig,
                             const float* __restrict__ epsb)
{
    int jj = blockIdx.x * 256 + threadIdx.x;
    if (jj >= HH + OO) return;
    int j = DD + jj;
    float acc = 0.f;
    for (int c = 0; c < 61; ++c) acc += g_s1_part[c * (HH + OO) + jj];
    g_vals1[jj] = tanhf(acc + bmu[j] + bsig[j] * epsb[j]);
}
__global__ void sweep2_part(const float* __restrict__ mu, const float* __restrict__ sig,
                            const float* __restrict__ eps)
{
    const int t = threadIdx.x;
    const int col = t & 7;
    const int lane = t >> 3;
    const int i0 = blockIdx.x * 257;
    const int j = DD + HH + col;
    float acc = 0.f;
    for (int r = lane; r < 257; r += 32) {
        int i = i0 + r;
        if (i < NN) {
            float vi = (i < DD) ? g_context[i] : g_vals1[i - DD];
            size_t off = (size_t)i * NN + j;
            acc += vi * (mu[off] + sig[off] * eps[off]);
        }
    }
    __shared__ float sh[256];
    sh[t] = acc;
    __syncthreads();
    for (int s = 128; s >= 8; s >>= 1) {
        if (t < s) sh[t] += sh[t + s];
        __syncthreads();
    }
    if (t < 8) g_s2_part[blockIdx.x * 8 + t] = sh[t];
}
__global__ void final_out(const float* __restrict__ bmu, const float* __restrict__ bsig,
                          const float* __restrict__ epsb, float* __restrict__ out)
{
    int t = threadIdx.x;
    if (t < OO) {
        float acc = 0.f;
        #pragma unroll
        for (int b = 0; b < 32; ++b) acc += g_s2_part[b * 8 + t];
        int j = DD + HH + t;
        float v = tanhf(acc + bmu[j] + bsig[j] * epsb[j]);
        out[t] = 1.0f / (1.0f + expf(-v));
    }
}

// ---------------- launcher ----------------
extern "C" void kernel_launch(void* const* d_in, const int* in_sizes, int n_in,
                              void* d_out, int out_size)
{
    const float* inp  = (const float*)d_in[0];
    const float* Wq   = (const float*)d_in[1];
    const float* bq   = (const float*)d_in[2];
    const float* Wk   = (const float*)d_in[3];
    const float* bk   = (const float*)d_in[4];
    const float* Wv   = (const float*)d_in[5];
    const float* bv   = (const float*)d_in[6];
    const float* wmu  = (const float*)d_in[7];
    const float* wsig = (const float*)d_in[8];
    const float* bmu  = (const float*)d_in[9];
    const float* bsig = (const float*)d_in[10];
    const float* epsb = (const float*)d_in[12];
    const float* epsw = (const float*)d_in[11];
    float* out = (float*)d_out;

    int8_t *xq0, *xq1, *wt0, *wt1, *qq0, *qq1, *kq0, *kq1;
    float *sX, *sQ, *sK, *q, *k, *sc;
    cudaGetSymbolAddress((void**)&xq0, g_xq0);
    cudaGetSymbolAddress((void**)&xq1, g_xq1);
    cudaGetSymbolAddress((void**)&wt0, g_wt0);
    cudaGetSymbolAddress((void**)&wt1, g_wt1);
    cudaGetSymbolAddress((void**)&qq0, g_qq0);
    cudaGetSymbolAddress((void**)&qq1, g_qq1);
    cudaGetSymbolAddress((void**)&kq0, g_kq0);
    cudaGetSymbolAddress((void**)&kq1, g_kq1);
    cudaGetSymbolAddress((void**)&sX, g_sX);
    cudaGetSymbolAddress((void**)&sQ, g_sQ);
    cudaGetSymbolAddress((void**)&sK, g_sK);
    cudaGetSymbolAddress((void**)&q, g_q);
    cudaGetSymbolAddress((void**)&k, g_k);
    cudaGetSymbolAddress((void**)&sc, g_scores);
    float* sW; cudaGetSymbolAddress((void**)&sW, g_sW);

    cudaFuncSetAttribute(tc_gemm8, cudaFuncAttributeMaxDynamicSharedMemorySize, SMEM8);

    const dim3 wmax_grid(31, 16);
    const dim3 qt_grid(WROWS / 64, KP / 32);
    const dim3 qkv_grid(WROWS / 64, MM / 128);   // 121 x 16
    const dim3 sc_grid(MM / 64, MM / 128);       // 32 x 16

    quant_rows<<<MM, 256>>>(inp, DD, xq0, xq1, sX);

    // q = inp @ Wq + bq
    wmax_part<<<wmax_grid, 256>>>(Wq);
    wmax_red<<<31, 256>>>();
    quantT_w<<<qt_grid, 256>>>(Wq, wt0, wt1);
    tc_gemm8<<<qkv_grid, 128, SMEM8>>>(xq0, xq1, wt0, wt1, sX, sW, bq, 1.f, q, DD);

    // k = inp @ Wk + bk
    wmax_part<<<wmax_grid, 256>>>(Wk);
    wmax_red<<<31, 256>>>();
    quantT_w<<<qt_grid, 256>>>(Wk, wt0, wt1);
    tc_gemm8<<<qkv_grid, 128, SMEM8>>>(xq0, xq1, wt0, wt1, sX, sW, bk, 1.f, k, DD);

    // scores = q @ k^T / sqrt(D)
    quant_rows<<<MM, 256>>>(q, DD, qq0, qq1, sQ);
    quant_rows<<<MM, 256>>>(k, DD, kq0, kq1, sK);
    tc_gemm8<<<sc_grid, 128, SMEM8>>>(qq0, qq1, kq0, kq1, sQ, sK, nullptr,
                                      rsqrtf((float)DD), sc, MM);

    softmax_rows<<<MM, 256>>>(sc);
    colsum_part<<<dim3(MM / 256, 16), 256>>>(sc);
    colsum_reduce<<<MM / 256, 256>>>();

    u_part<<<dim3((DD + 255) / 256, 16), 256>>>(inp);
    u_reduce<<<(DD + 255) / 256, 256>>>();
    ctx2_part<<<dim3((DD + 255) / 256, 16), 256>>>(Wv);
    ctx2_reduce<<<(DD + 255) / 256, 256>>>(bv);

    sweep1_part<<<dim3(3, 61), 256>>>(wmu, wsig, epsw);
    sweep1_final<<<3, 256>>>(bmu, bsig, epsb);
    sweep2_part<<<32, 256>>>(wmu, wsig, epsw);
    final_out<<<1, 32>>>(bmu, bsig, epsb, out);
}

// round 8
// speedup vs baseline: 2.5155x; 2.5155x over previous
#include <cuda_runtime.h>
#include <cuda_bf16.h>
#include <cstdint>
#include <math.h>

// ---------------- problem constants ----------------
#define MM 2048      // num_memories
#define DD 7686      // input size
#define HH 512
#define OO 8
#define NN 8206      // DD + HH + OO
#define KP 7744      // K padded to multiple of 32
#define WROWS 7936   // padded B rows for W^T (62 * 128)
#define BKC 32
#define KCHUNKS (KP / BKC)   // 242

// ---------------- small PTX helpers ----------------
__device__ __forceinline__ uint32_t smem_to_u32(const void* p) {
    uint32_t a;
    asm("{ .reg .u64 t; cvta.to.shared.u64 t, %1; cvt.u32.u64 %0, t; }"
        : "=r"(a) : "l"(p));
    return a;
}

__device__ __forceinline__ void cpa16(uint32_t s, const void* g) {
    asm volatile("cp.async.cg.shared.global [%0], [%1], 16;" :: "r"(s), "l"(g) : "memory");
}
#define CP_COMMIT() asm volatile("cp.async.commit_group;" ::: "memory")

__device__ __forceinline__ void ldsm4(uint32_t (&r)[4], uint32_t addr) {
    asm volatile("ldmatrix.sync.aligned.m8n8.x4.shared.b16 {%0,%1,%2,%3}, [%4];"
                 : "=r"(r[0]), "=r"(r[1]), "=r"(r[2]), "=r"(r[3]) : "r"(addr));
}

__device__ __forceinline__ void mma16816(float (&d)[4], const uint32_t (&a)[4],
                                         const uint32_t b0, const uint32_t b1) {
    asm volatile(
        "mma.sync.aligned.m16n8k16.row.col.f32.bf16.bf16.f32 "
        "{%0,%1,%2,%3}, {%4,%5,%6,%7}, {%8,%9}, {%0,%1,%2,%3};"
        : "+f"(d[0]), "+f"(d[1]), "+f"(d[2]), "+f"(d[3])
        : "r"(a[0]), "r"(a[1]), "r"(a[2]), "r"(a[3]), "r"(b0), "r"(b1));
}

// SW64 swizzle for 64B-wide smem rows (conflict-free ldmatrix)
__device__ __forceinline__ uint32_t sw_off(int row, int c) {
    uint32_t o = (uint32_t)(row * 64 + c * 16);
    return o ^ ((o >> 3) & 0x30);
}

// ---------------- device scratch ----------------
__device__ __nv_bfloat16 g_ihi[(size_t)MM * KP];
__device__ __nv_bfloat16 g_ilo[(size_t)MM * KP];
__device__ __nv_bfloat16 g_wtqhi[(size_t)WROWS * KP];
__device__ __nv_bfloat16 g_wtqlo[(size_t)WROWS * KP];
__device__ __nv_bfloat16 g_wtkhi[(size_t)WROWS * KP];
__device__ __nv_bfloat16 g_wtklo[(size_t)WROWS * KP];
__device__ __nv_bfloat16 g_qhi[(size_t)MM * KP];
__device__ __nv_bfloat16 g_qlo[(size_t)MM * KP];
__device__ __nv_bfloat16 g_khi[(size_t)MM * KP];
__device__ __nv_bfloat16 g_klo[(size_t)MM * KP];
__device__ float g_scores[(size_t)MM * MM];
__device__ float g_cs_part[16 * MM];
__device__ float g_colsum[MM];
__device__ float g_part[16 * DD];
__device__ float g_u[DD];
__device__ float g_context[DD];
__device__ float g_s1_part[61 * (HH + OO)];
__device__ float g_vals1[HH + OO];
__device__ float g_s2_part[32 * OO];

// ---------------- split fp32 -> bf16 hi/lo, pad cols to KP ----------------
__global__ void split_pad(const float* __restrict__ x,
                          __nv_bfloat16* __restrict__ hi,
                          __nv_bfloat16* __restrict__ lo, int cols)
{
    int c = blockIdx.x * 256 + threadIdx.x;
    if (c >= KP) return;
    int r = blockIdx.y;
    float v = (c < cols) ? x[(size_t)r * cols + c] : 0.f;
    __nv_bfloat16 h = __float2bfloat16(v);
    float rem = v - __bfloat162float(h);
    hi[(size_t)r * KP + c] = h;
    lo[(size_t)r * KP + c] = __float2bfloat16(rem);
}

// ---------------- transpose + split: W[k][n] -> Wt[n][k] bf16 hi/lo -------------
__global__ void transpose_split(const float* __restrict__ W,
                                __nv_bfloat16* __restrict__ Thi,
                                __nv_bfloat16* __restrict__ Tlo)
{
    __shared__ float s[32][33];
    const int tx = threadIdx.x;
    const int ty = threadIdx.y;
    const int n0 = blockIdx.x * 32;
    const int k0 = blockIdx.y * 32;

    #pragma unroll
    for (int i = 0; i < 4; ++i) {
        int a = ty + 8 * i;
        int k = k0 + a;
        int n = n0 + tx;
        s[a][tx] = (k < DD && n < DD) ? W[(size_t)k * DD + n] : 0.f;
    }
    __syncthreads();
    #pragma unroll
    for (int i = 0; i < 4; ++i) {
        int a = ty + 8 * i;
        float v = s[tx][a];
        __nv_bfloat16 h = __float2bfloat16(v);
        float rem = v - __bfloat162float(h);
        size_t off = (size_t)(n0 + a) * KP + (k0 + tx);
        Thi[off] = h;
        Tlo[off] = __float2bfloat16(rem);
    }
}

// ---------------- bf16x3 mma.sync GEMM, CTA tile 128x128, 4 warps ---------------
// Dual-B dispatch: blockIdx.x < nsplit -> (B1, bias1, C1 outputs),
// else (B2, bias2, C2) with rebased n0. Combines q & k GEMMs in one launch
// to remove one wave-quantization tail.
#define T_AHI 0
#define T_ALO 8192
#define T_BHI 16384
#define T_BLO 24576
#define STAGE_BYTES 32768
#define NSTAGE 3
#define SMEM_GEMM (NSTAGE * STAGE_BYTES)   // 98304

__global__ __launch_bounds__(128, 2)
void tc_gemm(const __nv_bfloat16* __restrict__ Ahi, const __nv_bfloat16* __restrict__ Alo,
             const __nv_bfloat16* __restrict__ B1hi, const __nv_bfloat16* __restrict__ B1lo,
             const __nv_bfloat16* __restrict__ B2hi, const __nv_bfloat16* __restrict__ B2lo,
             const float* __restrict__ bias1, const float* __restrict__ bias2,
             int nsplit, float scale,
             float* __restrict__ Cf, int Cld,
             __nv_bfloat16* __restrict__ C1hi, __nv_bfloat16* __restrict__ C1lo,
             __nv_bfloat16* __restrict__ C2hi, __nv_bfloat16* __restrict__ C2lo)
{
    extern __shared__ char smem[];
    const uint32_t sb = smem_to_u32(smem);
    const int t   = threadIdx.x;
    const int wid = t >> 5;
    const int lid = t & 31;
    const int m0 = blockIdx.y * 128;

    const __nv_bfloat16 *Bhi, *Blo;
    const float* bias;
    __nv_bfloat16 *Chi, *Clo;
    int n0;
    if ((int)blockIdx.x < nsplit) {
        n0 = blockIdx.x * 128;
        Bhi = B1hi; Blo = B1lo; bias = bias1; Chi = C1hi; Clo = C1lo;
    } else {
        n0 = (blockIdx.x - nsplit) * 128;
        Bhi = B2hi; Blo = B2lo; bias = bias2; Chi = C2hi; Clo = C2lo;
    }

    // loader slots: row = t>>2 (0..31), c = t&3 (16B units within 64B row)
    const int rl = t >> 2;
    const int cl = t & 3;
    const uint32_t soR[4] = { sw_off(rl, cl), sw_off(rl + 32, cl),
                              sw_off(rl + 64, cl), sw_off(rl + 96, cl) };

    float acc[4][8][4];
    #pragma unroll
    for (int a = 0; a < 4; ++a)
        #pragma unroll
        for (int b = 0; b < 8; ++b)
            #pragma unroll
            for (int c = 0; c < 4; ++c) acc[a][b][c] = 0.f;

    const char* pAhi = (const char*)Ahi;
    const char* pAlo = (const char*)Alo;
    const char* pBhi = (const char*)Bhi;
    const char* pBlo = (const char*)Blo;

    auto load_stage = [&](int kc, int slot) {
        const int k0 = kc * BKC;
        const uint32_t st = sb + slot * STAGE_BYTES;
        #pragma unroll
        for (int i = 0; i < 4; ++i) {
            const int r = rl + 32 * i;
            size_t ga = (((size_t)(m0 + r) * KP + k0 + cl * 8) << 1);
            size_t gb = (((size_t)(n0 + r) * KP + k0 + cl * 8) << 1);
            cpa16(st + T_AHI + soR[i], pAhi + ga);
            cpa16(st + T_ALO + soR[i], pAlo + ga);
            cpa16(st + T_BHI + soR[i], pBhi + gb);
            cpa16(st + T_BLO + soR[i], pBlo + gb);
        }
        CP_COMMIT();
    };

    const int wm = wid >> 1;       // 0..1 (m offset 64)
    const int wn = wid & 1;        // 0..1 (n offset 64)
    const int lrow = lid & 15;
    const int lcg  = lid >> 4;     // 0..1

    load_stage(0, 0);
    load_stage(1, 1);

    int slot = 0;                  // kc % 3
    int nslot = 2;                 // (kc+2) % 3
    for (int kc = 0; kc < KCHUNKS; ++kc) {
        asm volatile("cp.async.wait_group 1;" ::: "memory");
        __syncthreads();
        if (kc + 2 < KCHUNKS) load_stage(kc + 2, nslot);
        else CP_COMMIT();

        const uint32_t st = sb + slot * STAGE_BYTES;
        slot = (slot == 2) ? 0 : slot + 1;
        nslot = (nslot == 2) ? 0 : nslot + 1;

        #pragma unroll
        for (int ks = 0; ks < 2; ++ks) {
            const int ccol = ks * 2 + lcg;
            uint32_t ahi[4][4], alo[4][4];
            #pragma unroll
            for (int mt = 0; mt < 4; ++mt) {
                uint32_t so = sw_off(wm * 64 + mt * 16 + lrow, ccol);
                ldsm4(ahi[mt], st + T_AHI + so);
                ldsm4(alo[mt], st + T_ALO + so);
            }
            uint32_t bhi[8][2], blo[8][2];
            #pragma unroll
            for (int p = 0; p < 4; ++p) {
                uint32_t so = sw_off(wn * 64 + p * 16 + lrow, ccol);
                uint32_t r[4];
                ldsm4(r, st + T_BHI + so);
                bhi[2*p][0] = r[0]; bhi[2*p][1] = r[2];
                bhi[2*p+1][0] = r[1]; bhi[2*p+1][1] = r[3];
                ldsm4(r, st + T_BLO + so);
                blo[2*p][0] = r[0]; blo[2*p][1] = r[2];
                blo[2*p+1][0] = r[1]; blo[2*p+1][1] = r[3];
            }
            #pragma unroll
            for (int mt = 0; mt < 4; ++mt)
                #pragma unroll
                for (int q = 0; q < 8; ++q) {
                    float (&d)[4] = acc[mt][q];
                    mma16816(d, ahi[mt], bhi[q][0], bhi[q][1]);
                    mma16816(d, ahi[mt], blo[q][0], blo[q][1]);
                    mma16816(d, alo[mt], bhi[q][0], bhi[q][1]);
                }
        }
    }

    // ---- epilogue ----
    const int g  = lid >> 2;
    const int t4 = lid & 3;
    #pragma unroll
    for (int mt = 0; mt < 4; ++mt) {
        #pragma unroll
        for (int nt = 0; nt < 8; ++nt) {
            const int m = m0 + wm * 64 + mt * 16 + g;
            const int n = n0 + wn * 64 + nt * 8 + t4 * 2;
            float d0 = acc[mt][nt][0], d1 = acc[mt][nt][1];
            float d2 = acc[mt][nt][2], d3 = acc[mt][nt][3];
            if (Cf) {
                if (n + 1 < Cld) {
                    float2 v0 = make_float2(d0 * scale, d1 * scale);
                    float2 v1 = make_float2(d2 * scale, d3 * scale);
                    *(float2*)(Cf + (size_t)m * Cld + n) = v0;
                    *(float2*)(Cf + (size_t)(m + 8) * Cld + n) = v1;
                }
            } else {
                if (n < KP) {
                    float b0 = (n     < DD) ? bias[n]     : 0.f;
                    float b1 = (n + 1 < DD) ? bias[n + 1] : 0.f;
                    float v0 = (n     < DD) ? d0 + b0 : 0.f;
                    float v1 = (n + 1 < DD) ? d1 + b1 : 0.f;
                    float v2 = (n     < DD) ? d2 + b0 : 0.f;
                    float v3 = (n + 1 < DD) ? d3 + b1 : 0.f;
                    __nv_bfloat16 h0 = __float2bfloat16(v0);
                    __nv_bfloat16 h1 = __float2bfloat16(v1);
                    __nv_bfloat16 h2 = __float2bfloat16(v2);
                    __nv_bfloat16 h3 = __float2bfloat16(v3);
                    __nv_bfloat162 hp0; hp0.x = h0; hp0.y = h1;
                    __nv_bfloat162 hp1; hp1.x = h2; hp1.y = h3;
                    __nv_bfloat162 lp0;
                    lp0.x = __float2bfloat16(v0 - __bfloat162float(h0));
                    lp0.y = __float2bfloat16(v1 - __bfloat162float(h1));
                    __nv_bfloat162 lp1;
                    lp1.x = __float2bfloat16(v2 - __bfloat162float(h2));
                    lp1.y = __float2bfloat16(v3 - __bfloat162float(h3));
                    *(__nv_bfloat162*)(Chi + (size_t)m * KP + n) = hp0;
                    *(__nv_bfloat162*)(Chi + (size_t)(m + 8) * KP + n) = hp1;
                    *(__nv_bfloat162*)(Clo + (size_t)m * KP + n) = lp0;
                    *(__nv_bfloat162*)(Clo + (size_t)(m + 8) * KP + n) = lp1;
                }
            }
        }
    }
}

// ---------------- row softmax (in place), row length MM ------------------------
__global__ void softmax_rows(float* __restrict__ S)
{
    const int row = blockIdx.x;
    const int t = threadIdx.x;
    float* r = S + (size_t)row * MM;
    float v[8];
    #pragma unroll
    for (int i = 0; i < 8; ++i) v[i] = r[i * 256 + t];

    float mx = v[0];
    #pragma unroll
    for (int i = 1; i < 8; ++i) mx = fmaxf(mx, v[i]);

    __shared__ float sh[32];
    #pragma unroll
    for (int o = 16; o > 0; o >>= 1) mx = fmaxf(mx, __shfl_xor_sync(0xffffffff, mx, o));
    if ((t & 31) == 0) sh[t >> 5] = mx;
    __syncthreads();
    if (t < 32) {
        float m = (t < 8) ? sh[t] : -INFINITY;
        #pragma unroll
        for (int o = 4; o > 0; o >>= 1) m = fmaxf(m, __shfl_xor_sync(0xffffffff, m, o));
        sh[0] = m;
    }
    __syncthreads();
    mx = sh[0];
    __syncthreads();

    float sum = 0.f;
    #pragma unroll
    for (int i = 0; i < 8; ++i) { v[i] = expf(v[i] - mx); sum += v[i]; }
    #pragma unroll
    for (int o = 16; o > 0; o >>= 1) sum += __shfl_xor_sync(0xffffffff, sum, o);
    if ((t & 31) == 0) sh[t >> 5] = sum;
    __syncthreads();
    if (t < 32) {
        float s = (t < 8) ? sh[t] : 0.f;
        #pragma unroll
        for (int o = 4; o > 0; o >>= 1) s += __shfl_xor_sync(0xffffffff, s, o);
        sh[0] = s;
    }
    __syncthreads();
    float inv = 1.f / sh[0];
    #pragma unroll
    for (int i = 0; i < 8; ++i) r[i * 256 + t] = v[i] * inv;
}

// ---------------- column sums of P ----------------
__global__ void colsum_part(const float* __restrict__ P)
{
    int j = blockIdx.x * 256 + threadIdx.x;
    int r0 = blockIdx.y * 128;
    float acc = 0.f;
    for (int r = 0; r < 128; ++r) acc += P[(size_t)(r0 + r) * MM + j];
    g_cs_part[blockIdx.y * MM + j] = acc;
}

__global__ void colsum_reduce()
{
    int j = blockIdx.x * 256 + threadIdx.x;
    float acc = 0.f;
    #pragma unroll
    for (int c = 0; c < 16; ++c) acc += g_cs_part[c * MM + j];
    g_colsum[j] = acc;
}

// ---------------- u = (colsum @ inp) / M ----------------
__global__ void u_part(const float* __restrict__ X)
{
    int j = blockIdx.x * 256 + threadIdx.x;
    if (j >= DD) return;
    int r0 = blockIdx.y * 128;
    float acc = 0.f;
    for (int r = 0; r < 128; ++r) {
        int l = r0 + r;
        acc += g_colsum[l] * X[(size_t)l * DD + j];
    }
    g_part[blockIdx.y * DD + j] = acc;
}

__global__ void u_reduce()
{
    int j = blockIdx.x * 256 + threadIdx.x;
    if (j >= DD) return;
    float acc = 0.f;
    #pragma unroll
    for (int c = 0; c < 16; ++c) acc += g_part[c * DD + j];
    g_u[j] = acc * (1.0f / (float)MM);
}

// ---------------- context = u @ Wv + bv ----------------
__global__ void ctx2_part(const float* __restrict__ Wv)
{
    int j = blockIdx.x * 256 + threadIdx.x;
    if (j >= DD) return;
    int i0 = blockIdx.y * 481;
    float acc = 0.f;
    for (int r = 0; r < 481; ++r) {
        int i = i0 + r;
        if (i < DD) acc += g_u[i] * Wv[(size_t)i * DD + j];
    }
    g_part[blockIdx.y * DD + j] = acc;
}

__global__ void ctx2_reduce(const float* __restrict__ bv)
{
    int j = blockIdx.x * 256 + threadIdx.x;
    if (j >= DD) return;
    float acc = 0.f;
    #pragma unroll
    for (int c = 0; c < 16; ++c) acc += g_part[c * DD + j];
    g_context[j] = acc + bv[j];
}

// ---------------- sweep 1: cols [DD, NN), rows i<DD ----------------
__global__ void sweep1_part(const float* __restrict__ mu, const float* __restrict__ sig,
                            const float* __restrict__ eps)
{
    int jj = blockIdx.x * 256 + threadIdx.x;
    if (jj >= HH + OO) return;
    int j = DD + jj;
    int i0 = blockIdx.y * 126;
    float acc = 0.f;
    for (int r = 0; r < 126; ++r) {
        int i = i0 + r;
        size_t off = (size_t)i * NN + j;
        acc += g_context[i] * (mu[off] + sig[off] * eps[off]);
    }
    g_s1_part[blockIdx.y * (HH + OO) + jj] = acc;
}

__global__ void sweep1_final(const float* __restrict__ bmu, const float* __restrict__ bsig,
                             const float* __restrict__ epsb)
{
    int jj = blockIdx.x * 256 + threadIdx.x;
    if (jj >= HH + OO) return;
    int j = DD + jj;
    float acc = 0.f;
    for (int c = 0; c < 61; ++c) acc += g_s1_part[c * (HH + OO) + jj];
    g_vals1[jj] = tanhf(acc + bmu[j] + bsig[j] * epsb[j]);
}

// ---------------- sweep 2: cols [DD+HH, NN), all rows ----------------
__global__ void sweep2_part(const float* __restrict__ mu, const float* __restrict__ sig,
                            const float* __restrict__ eps)
{
    const int t = threadIdx.x;
    const int col = t & 7;
    const int lane = t >> 3;
    const int i0 = blockIdx.x * 257;
    const int j = DD + HH + col;
    float acc = 0.f;
    for (int r = lane; r < 257; r += 32) {
        int i = i0 + r;
        if (i < NN) {
            float vi = (i < DD) ? g_context[i] : g_vals1[i - DD];
            size_t off = (size_t)i * NN + j;
            acc += vi * (mu[off] + sig[off] * eps[off]);
        }
    }
    __shared__ float sh[256];
    sh[t] = acc;
    __syncthreads();
    for (int s = 128; s >= 8; s >>= 1) {
        if (t < s) sh[t] += sh[t + s];
        __syncthreads();
    }
    if (t < 8) g_s2_part[blockIdx.x * 8 + t] = sh[t];
}

__global__ void final_out(const float* __restrict__ bmu, const float* __restrict__ bsig,
                          const float* __restrict__ epsb, float* __restrict__ out)
{
    int t = threadIdx.x;
    if (t < OO) {
        float acc = 0.f;
        #pragma unroll
        for (int b = 0; b < 32; ++b) acc += g_s2_part[b * 8 + t];
        int j = DD + HH + t;
        float v = tanhf(acc + bmu[j] + bsig[j] * epsb[j]);
        out[t] = 1.0f / (1.0f + expf(-v));
    }
}

// ---------------- launcher -------------------------------------------------------
extern "C" void kernel_launch(void* const* d_in, const int* in_sizes, int n_in,
                              void* d_out, int out_size)
{
    const float* inp  = (const float*)d_in[0];
    const float* Wq   = (const float*)d_in[1];
    const float* bq   = (const float*)d_in[2];
    const float* Wk   = (const float*)d_in[3];
    const float* bk   = (const float*)d_in[4];
    const float* Wv   = (const float*)d_in[5];
    const float* bv   = (const float*)d_in[6];
    const float* wmu  = (const float*)d_in[7];
    const float* wsig = (const float*)d_in[8];
    const float* bmu  = (const float*)d_in[9];
    const float* bsig = (const float*)d_in[10];
    const float* epsw = (const float*)d_in[11];
    const float* epsb = (const float*)d_in[12];
    float* out = (float*)d_out;

    __nv_bfloat16 *ihi, *ilo, *wtqhi, *wtqlo, *wtkhi, *wtklo;
    __nv_bfloat16 *qhi, *qlo, *khi, *klo;
    float *sc;
    cudaGetSymbolAddress((void**)&ihi,   g_ihi);
    cudaGetSymbolAddress((void**)&ilo,   g_ilo);
    cudaGetSymbolAddress((void**)&wtqhi, g_wtqhi);
    cudaGetSymbolAddress((void**)&wtqlo, g_wtqlo);
    cudaGetSymbolAddress((void**)&wtkhi, g_wtkhi);
    cudaGetSymbolAddress((void**)&wtklo, g_wtklo);
    cudaGetSymbolAddress((void**)&qhi,   g_qhi);
    cudaGetSymbolAddress((void**)&qlo,   g_qlo);
    cudaGetSymbolAddress((void**)&khi,   g_khi);
    cudaGetSymbolAddress((void**)&klo,   g_klo);
    cudaGetSymbolAddress((void**)&sc,    g_scores);

    cudaFuncSetAttribute(tc_gemm, cudaFuncAttributeMaxDynamicSharedMemorySize,
                         SMEM_GEMM);

    const dim3 split_grid((KP + 255) / 256, MM);
    const dim3 tr_grid(WROWS / 32, KP / 32);
    const dim3 tr_blk(32, 8);
    const dim3 qk_grid(2 * (WROWS / 128), MM / 128);   // 124 x 16 (q & k fused)
    const dim3 sc_grid(MM / 128, MM / 128);            // 16 x 16

    // input split to bf16 hi/lo
    split_pad<<<split_grid, 256>>>(inp, ihi, ilo, DD);

    // transpose+split both weight matrices
    transpose_split<<<tr_grid, tr_blk>>>(Wq, wtqhi, wtqlo);
    transpose_split<<<tr_grid, tr_blk>>>(Wk, wtkhi, wtklo);

    // q = inp @ Wq + bq  AND  k = inp @ Wk + bk  (one launch, bf16 hi/lo out)
    tc_gemm<<<qk_grid, 128, SMEM_GEMM>>>(ihi, ilo,
                                         wtqhi, wtqlo, wtkhi, wtklo,
                                         bq, bk, WROWS / 128, 1.f,
                                         nullptr, 0, qhi, qlo, khi, klo);

    // scores = q @ k^T / sqrt(D)  (fp32 out)
    tc_gemm<<<sc_grid, 128, SMEM_GEMM>>>(qhi, qlo,
                                         khi, klo, nullptr, nullptr,
                                         nullptr, nullptr, 1 << 20,
                                         rsqrtf((float)DD),
                                         sc, MM, nullptr, nullptr, nullptr, nullptr);

    softmax_rows<<<MM, 256>>>(sc);

    colsum_part<<<dim3(MM / 256, 16), 256>>>(sc);
    colsum_reduce<<<MM / 256, 256>>>();

    // context = ((colsum/M) @ inp) @ Wv + bv
    u_part<<<dim3((DD + 255) / 256, 16), 256>>>(inp);
    u_reduce<<<(DD + 255) / 256, 256>>>();
    ctx2_part<<<dim3((DD + 255) / 256, 16), 256>>>(Wv);
    ctx2_reduce<<<(DD + 255) / 256, 256>>>(bv);

    sweep1_part<<<dim3(3, 61), 256>>>(wmu, wsig, epsw);
    sweep1_final<<<3, 256>>>(bmu, bsig, epsb);

    sweep2_part<<<32, 256>>>(wmu, wsig, epsw);
    final_out<<<1, 32>>>(bmu, bsig, epsb, out);
}

// round 9
// speedup vs baseline: 2.5261x; 1.0042x over previous
#include <cuda_runtime.h>
#include <cuda_bf16.h>
#include <cstdint>
#include <math.h>

// ---------------- problem constants ----------------
#define MM 2048      // num_memories
#define DD 7686      // input size
#define HH 512
#define OO 8
#define NN 8206      // DD + HH + OO
#define KP 7744      // K padded to multiple of 32
#define WROWS 7936   // padded B rows for W^T (62 * 128)
#define BKC 32
#define KCHUNKS (KP / BKC)   // 242

// ---------------- small PTX helpers ----------------
__device__ __forceinline__ uint32_t smem_to_u32(const void* p) {
    uint32_t a;
    asm("{ .reg .u64 t; cvta.to.shared.u64 t, %1; cvt.u32.u64 %0, t; }"
        : "=r"(a) : "l"(p));
    return a;
}

__device__ __forceinline__ void cpa16(uint32_t s, const void* g) {
    asm volatile("cp.async.cg.shared.global [%0], [%1], 16;" :: "r"(s), "l"(g) : "memory");
}
#define CP_COMMIT() asm volatile("cp.async.commit_group;" ::: "memory")

__device__ __forceinline__ void ldsm4(uint32_t (&r)[4], uint32_t addr) {
    asm volatile("ldmatrix.sync.aligned.m8n8.x4.shared.b16 {%0,%1,%2,%3}, [%4];"
                 : "=r"(r[0]), "=r"(r[1]), "=r"(r[2]), "=r"(r[3]) : "r"(addr));
}

__device__ __forceinline__ void mma16816(float (&d)[4], const uint32_t (&a)[4],
                                         const uint32_t b0, const uint32_t b1) {
    asm volatile(
        "mma.sync.aligned.m16n8k16.row.col.f32.bf16.bf16.f32 "
        "{%0,%1,%2,%3}, {%4,%5,%6,%7}, {%8,%9}, {%0,%1,%2,%3};"
        : "+f"(d[0]), "+f"(d[1]), "+f"(d[2]), "+f"(d[3])
        : "r"(a[0]), "r"(a[1]), "r"(a[2]), "r"(a[3]), "r"(b0), "r"(b1));
}

// SW64 swizzle for 64B-wide smem rows (conflict-free ldmatrix)
__device__ __forceinline__ uint32_t sw_off(int row, int c) {
    uint32_t o = (uint32_t)(row * 64 + c * 16);
    return o ^ ((o >> 3) & 0x30);
}

// ---------------- device scratch ----------------
__device__ __nv_bfloat16 g_ihi[(size_t)MM * KP];
__device__ __nv_bfloat16 g_ilo[(size_t)MM * KP];
__device__ __nv_bfloat16 g_wtqhi[(size_t)WROWS * KP];
__device__ __nv_bfloat16 g_wtqlo[(size_t)WROWS * KP];
__device__ __nv_bfloat16 g_wtkhi[(size_t)WROWS * KP];
__device__ __nv_bfloat16 g_wtklo[(size_t)WROWS * KP];
__device__ __nv_bfloat16 g_qhi[(size_t)MM * KP];
__device__ __nv_bfloat16 g_qlo[(size_t)MM * KP];
__device__ __nv_bfloat16 g_khi[(size_t)MM * KP];
__device__ __nv_bfloat16 g_klo[(size_t)MM * KP];
__device__ float g_scores[(size_t)MM * MM];
__device__ float g_cs_part[16 * MM];
__device__ float g_colsum[MM];
__device__ float g_part[16 * DD];
__device__ float g_u[DD];
__device__ float g_context[DD];
__device__ float g_s1_part[61 * (HH + OO)];
__device__ float g_vals1[HH + OO];
__device__ float g_s2_part[32 * OO];

// ---------------- split fp32 -> bf16 hi/lo, pad cols to KP ----------------
__global__ void split_pad(const float* __restrict__ x,
                          __nv_bfloat16* __restrict__ hi,
                          __nv_bfloat16* __restrict__ lo, int cols)
{
    int c = blockIdx.x * 256 + threadIdx.x;
    if (c >= KP) return;
    int r = blockIdx.y;
    float v = (c < cols) ? x[(size_t)r * cols + c] : 0.f;
    __nv_bfloat16 h = __float2bfloat16(v);
    float rem = v - __bfloat162float(h);
    hi[(size_t)r * KP + c] = h;
    lo[(size_t)r * KP + c] = __float2bfloat16(rem);
}

// ---------------- transpose + split: W[k][n] -> Wt[n][k] bf16 hi/lo -------------
__global__ void transpose_split(const float* __restrict__ W,
                                __nv_bfloat16* __restrict__ Thi,
                                __nv_bfloat16* __restrict__ Tlo)
{
    __shared__ float s[32][33];
    const int tx = threadIdx.x;
    const int ty = threadIdx.y;
    const int n0 = blockIdx.x * 32;
    const int k0 = blockIdx.y * 32;

    #pragma unroll
    for (int i = 0; i < 4; ++i) {
        int a = ty + 8 * i;
        int k = k0 + a;
        int n = n0 + tx;
        s[a][tx] = (k < DD && n < DD) ? W[(size_t)k * DD + n] : 0.f;
    }
    __syncthreads();
    #pragma unroll
    for (int i = 0; i < 4; ++i) {
        int a = ty + 8 * i;
        float v = s[tx][a];
        __nv_bfloat16 h = __float2bfloat16(v);
        float rem = v - __bfloat162float(h);
        size_t off = (size_t)(n0 + a) * KP + (k0 + tx);
        Thi[off] = h;
        Tlo[off] = __float2bfloat16(rem);
    }
}

// ---------------- bf16x3 mma.sync GEMM, CTA tile 128x128, 4 warps ---------------
// Dual-B dispatch (q & k fused). Inner loop software-pipelines B-fragment
// ldmatrix under the mma stream (register double-buffer) to fill the tensor pipe.
#define T_AHI 0
#define T_ALO 8192
#define T_BHI 16384
#define T_BLO 24576
#define STAGE_BYTES 32768
#define NSTAGE 3
#define SMEM_GEMM (NSTAGE * STAGE_BYTES)   // 98304

__global__ __launch_bounds__(128, 2)
void tc_gemm(const __nv_bfloat16* __restrict__ Ahi, const __nv_bfloat16* __restrict__ Alo,
             const __nv_bfloat16* __restrict__ B1hi, const __nv_bfloat16* __restrict__ B1lo,
             const __nv_bfloat16* __restrict__ B2hi, const __nv_bfloat16* __restrict__ B2lo,
             const float* __restrict__ bias1, const float* __restrict__ bias2,
             int nsplit, float scale,
             float* __restrict__ Cf, int Cld,
             __nv_bfloat16* __restrict__ C1hi, __nv_bfloat16* __restrict__ C1lo,
             __nv_bfloat16* __restrict__ C2hi, __nv_bfloat16* __restrict__ C2lo)
{
    extern __shared__ char smem[];
    const uint32_t sb = smem_to_u32(smem);
    const int t   = threadIdx.x;
    const int wid = t >> 5;
    const int lid = t & 31;
    const int m0 = blockIdx.y * 128;

    const __nv_bfloat16 *Bhi, *Blo;
    const float* bias;
    __nv_bfloat16 *Chi, *Clo;
    int n0;
    if ((int)blockIdx.x < nsplit) {
        n0 = blockIdx.x * 128;
        Bhi = B1hi; Blo = B1lo; bias = bias1; Chi = C1hi; Clo = C1lo;
    } else {
        n0 = (blockIdx.x - nsplit) * 128;
        Bhi = B2hi; Blo = B2lo; bias = bias2; Chi = C2hi; Clo = C2lo;
    }

    const int rl = t >> 2;
    const int cl = t & 3;
    const uint32_t soR[4] = { sw_off(rl, cl), sw_off(rl + 32, cl),
                              sw_off(rl + 64, cl), sw_off(rl + 96, cl) };

    float acc[4][8][4];
    #pragma unroll
    for (int a = 0; a < 4; ++a)
        #pragma unroll
        for (int b = 0; b < 8; ++b)
            #pragma unroll
            for (int c = 0; c < 4; ++c) acc[a][b][c] = 0.f;

    const char* pAhi = (const char*)Ahi;
    const char* pAlo = (const char*)Alo;
    const char* pBhi = (const char*)Bhi;
    const char* pBlo = (const char*)Blo;

    auto load_stage = [&](int kc, int slot) {
        const int k0 = kc * BKC;
        const uint32_t st = sb + slot * STAGE_BYTES;
        #pragma unroll
        for (int i = 0; i < 4; ++i) {
            const int r = rl + 32 * i;
            size_t ga = (((size_t)(m0 + r) * KP + k0 + cl * 8) << 1);
            size_t gb = (((size_t)(n0 + r) * KP + k0 + cl * 8) << 1);
            cpa16(st + T_AHI + soR[i], pAhi + ga);
            cpa16(st + T_ALO + soR[i], pAlo + ga);
            cpa16(st + T_BHI + soR[i], pBhi + gb);
            cpa16(st + T_BLO + soR[i], pBlo + gb);
        }
        CP_COMMIT();
    };

    const int wm = wid >> 1;       // 0..1 (m offset 64)
    const int wn = wid & 1;        // 0..1 (n offset 64)
    const int lrow = lid & 15;
    const int lcg  = lid >> 4;     // 0..1

    load_stage(0, 0);
    load_stage(1, 1);

    int slot = 0;                  // kc % 3
    int nslot = 2;                 // (kc+2) % 3
    for (int kc = 0; kc < KCHUNKS; ++kc) {
        asm volatile("cp.async.wait_group 1;" ::: "memory");
        __syncthreads();
        if (kc + 2 < KCHUNKS) load_stage(kc + 2, nslot);
        else CP_COMMIT();

        const uint32_t st = sb + slot * STAGE_BYTES;
        slot = (slot == 2) ? 0 : slot + 1;
        nslot = (nslot == 2) ? 0 : nslot + 1;

        #pragma unroll
        for (int ks = 0; ks < 2; ++ks) {
            const int ccol = ks * 2 + lcg;
            uint32_t ahi[4][4], alo[4][4];
            #pragma unroll
            for (int mt = 0; mt < 4; ++mt) {
                uint32_t so = sw_off(wm * 64 + mt * 16 + lrow, ccol);
                ldsm4(ahi[mt], st + T_AHI + so);
                ldsm4(alo[mt], st + T_ALO + so);
            }
            // B fragment double-buffer: ldsm of pair p+1 issues before the
            // mma block of pair p, so LSU latency hides under tensor issue.
            uint32_t bh[2][4], bl[2][4];
            {
                uint32_t so = sw_off(wn * 64 + lrow, ccol);
                ldsm4(bh[0], st + T_BHI + so);
                ldsm4(bl[0], st + T_BLO + so);
            }
            #pragma unroll
            for (int p = 0; p < 4; ++p) {
                const int cur = p & 1;
                const int nxt = cur ^ 1;
                if (p < 3) {
                    uint32_t so = sw_off(wn * 64 + (p + 1) * 16 + lrow, ccol);
                    ldsm4(bh[nxt], st + T_BHI + so);
                    ldsm4(bl[nxt], st + T_BLO + so);
                }
                #pragma unroll
                for (int mt = 0; mt < 4; ++mt) {
                    float (&d0)[4] = acc[mt][2 * p];
                    float (&d1)[4] = acc[mt][2 * p + 1];
                    mma16816(d0, ahi[mt], bh[cur][0], bh[cur][2]);
                    mma16816(d0, ahi[mt], bl[cur][0], bl[cur][2]);
                    mma16816(d0, alo[mt], bh[cur][0], bh[cur][2]);
                    mma16816(d1, ahi[mt], bh[cur][1], bh[cur][3]);
                    mma16816(d1, ahi[mt], bl[cur][1], bl[cur][3]);
                    mma16816(d1, alo[mt], bh[cur][1], bh[cur][3]);
                }
            }
        }
    }

    // ---- epilogue ----
    const int g  = lid >> 2;
    const int t4 = lid & 3;
    #pragma unroll
    for (int mt = 0; mt < 4; ++mt) {
        #pragma unroll
        for (int nt = 0; nt < 8; ++nt) {
            const int m = m0 + wm * 64 + mt * 16 + g;
            const int n = n0 + wn * 64 + nt * 8 + t4 * 2;
            float d0 = acc[mt][nt][0], d1 = acc[mt][nt][1];
            float d2 = acc[mt][nt][2], d3 = acc[mt][nt][3];
            if (Cf) {
                if (n + 1 < Cld) {
                    float2 v0 = make_float2(d0 * scale, d1 * scale);
                    float2 v1 = make_float2(d2 * scale, d3 * scale);
                    *(float2*)(Cf + (size_t)m * Cld + n) = v0;
                    *(float2*)(Cf + (size_t)(m + 8) * Cld + n) = v1;
                }
            } else {
                if (n < KP) {
                    float b0 = (n     < DD) ? bias[n]     : 0.f;
                    float b1 = (n + 1 < DD) ? bias[n + 1] : 0.f;
                    float v0 = (n     < DD) ? d0 + b0 : 0.f;
                    float v1 = (n + 1 < DD) ? d1 + b1 : 0.f;
                    float v2 = (n     < DD) ? d2 + b0 : 0.f;
                    float v3 = (n + 1 < DD) ? d3 + b1 : 0.f;
                    __nv_bfloat16 h0 = __float2bfloat16(v0);
                    __nv_bfloat16 h1 = __float2bfloat16(v1);
                    __nv_bfloat16 h2 = __float2bfloat16(v2);
                    __nv_bfloat16 h3 = __float2bfloat16(v3);
                    __nv_bfloat162 hp0; hp0.x = h0; hp0.y = h1;
                    __nv_bfloat162 hp1; hp1.x = h2; hp1.y = h3;
                    __nv_bfloat162 lp0;
                    lp0.x = __float2bfloat16(v0 - __bfloat162float(h0));
                    lp0.y = __float2bfloat16(v1 - __bfloat162float(h1));
                    __nv_bfloat162 lp1;
                    lp1.x = __float2bfloat16(v2 - __bfloat162float(h2));
                    lp1.y = __float2bfloat16(v3 - __bfloat162float(h3));
                    *(__nv_bfloat162*)(Chi + (size_t)m * KP + n) = hp0;
                    *(__nv_bfloat162*)(Chi + (size_t)(m + 8) * KP + n) = hp1;
                    *(__nv_bfloat162*)(Clo + (size_t)m * KP + n) = lp0;
                    *(__nv_bfloat162*)(Clo + (size_t)(m + 8) * KP + n) = lp1;
                }
            }
        }
    }
}

// ---------------- row softmax (in place), row length MM ------------------------
__global__ void softmax_rows(float* __restrict__ S)
{
    const int row = blockIdx.x;
    const int t = threadIdx.x;
    float* r = S + (size_t)row * MM;
    float v[8];
    #pragma unroll
    for (int i = 0; i < 8; ++i) v[i] = r[i * 256 + t];

    float mx = v[0];
    #pragma unroll
    for (int i = 1; i < 8; ++i) mx = fmaxf(mx, v[i]);

    __shared__ float sh[32];
    #pragma unroll
    for (int o = 16; o > 0; o >>= 1) mx = fmaxf(mx, __shfl_xor_sync(0xffffffff, mx, o));
    if ((t & 31) == 0) sh[t >> 5] = mx;
    __syncthreads();
    if (t < 32) {
        float m = (t < 8) ? sh[t] : -INFINITY;
        #pragma unroll
        for (int o = 4; o > 0; o >>= 1) m = fmaxf(m, __shfl_xor_sync(0xffffffff, m, o));
        sh[0] = m;
    }
    __syncthreads();
    mx = sh[0];
    __syncthreads();

    float sum = 0.f;
    #pragma unroll
    for (int i = 0; i < 8; ++i) { v[i] = expf(v[i] - mx); sum += v[i]; }
    #pragma unroll
    for (int o = 16; o > 0; o >>= 1) sum += __shfl_xor_sync(0xffffffff, sum, o);
    if ((t & 31) == 0) sh[t >> 5] = sum;
    __syncthreads();
    if (t < 32) {
        float s = (t < 8) ? sh[t] : 0.f;
        #pragma unroll
        for (int o = 4; o > 0; o >>= 1) s += __shfl_xor_sync(0xffffffff, s, o);
        sh[0] = s;
    }
    __syncthreads();
    float inv = 1.f / sh[0];
    #pragma unroll
    for (int i = 0; i < 8; ++i) r[i * 256 + t] = v[i] * inv;
}

// ---------------- column sums of P ----------------
__global__ void colsum_part(const float* __restrict__ P)
{
    int j = blockIdx.x * 256 + threadIdx.x;
    int r0 = blockIdx.y * 128;
    float acc = 0.f;
    for (int r = 0; r < 128; ++r) acc += P[(size_t)(r0 + r) * MM + j];
    g_cs_part[blockIdx.y * MM + j] = acc;
}

__global__ void colsum_reduce()
{
    int j = blockIdx.x * 256 + threadIdx.x;
    float acc = 0.f;
    #pragma unroll
    for (int c = 0; c < 16; ++c) acc += g_cs_part[c * MM + j];
    g_colsum[j] = acc;
}

// ---------------- u = (colsum @ inp) / M ----------------
__global__ void u_part(const float* __restrict__ X)
{
    int j = blockIdx.x * 256 + threadIdx.x;
    if (j >= DD) return;
    int r0 = blockIdx.y * 128;
    float acc = 0.f;
    for (int r = 0; r < 128; ++r) {
        int l = r0 + r;
        acc += g_colsum[l] * X[(size_t)l * DD + j];
    }
    g_part[blockIdx.y * DD + j] = acc;
}

__global__ void u_reduce()
{
    int j = blockIdx.x * 256 + threadIdx.x;
    if (j >= DD) return;
    float acc = 0.f;
    #pragma unroll
    for (int c = 0; c < 16; ++c) acc += g_part[c * DD + j];
    g_u[j] = acc * (1.0f / (float)MM);
}

// ---------------- context = u @ Wv + bv ----------------
__global__ void ctx2_part(const float* __restrict__ Wv)
{
    int j = blockIdx.x * 256 + threadIdx.x;
    if (j >= DD) return;
    int i0 = blockIdx.y * 481;
    float acc = 0.f;
    for (int r = 0; r < 481; ++r) {
        int i = i0 + r;
        if (i < DD) acc += g_u[i] * Wv[(size_t)i * DD + j];
    }
    g_part[blockIdx.y * DD + j] = acc;
}

__global__ void ctx2_reduce(const float* __restrict__ bv)
{
    int j = blockIdx.x * 256 + threadIdx.x;
    if (j >= DD) return;
    float acc = 0.f;
    #pragma unroll
    for (int c = 0; c < 16; ++c) acc += g_part[c * DD + j];
    g_context[j] = acc + bv[j];
}

// ---------------- sweep 1: cols [DD, NN), rows i<DD ----------------
__global__ void sweep1_part(const float* __restrict__ mu, const float* __restrict__ sig,
                            const float* __restrict__ eps)
{
    int jj = blockIdx.x * 256 + threadIdx.x;
    if (jj >= HH + OO) return;
    int j = DD + jj;
    int i0 = blockIdx.y * 126;
    float acc = 0.f;
    for (int r = 0; r < 126; ++r) {
        int i = i0 + r;
        size_t off = (size_t)i * NN + j;
        acc += g_context[i] * (mu[off] + sig[off] * eps[off]);
    }
    g_s1_part[blockIdx.y * (HH + OO) + jj] = acc;
}

__global__ void sweep1_final(const float* __restrict__ bmu, const float* __restrict__ bsig,
                             const float* __restrict__ epsb)
{
    int jj = blockIdx.x * 256 + threadIdx.x;
    if (jj >= HH + OO) return;
    int j = DD + jj;
    float acc = 0.f;
    for (int c = 0; c < 61; ++c) acc += g_s1_part[c * (HH + OO) + jj];
    g_vals1[jj] = tanhf(acc + bmu[j] + bsig[j] * epsb[j]);
}

// ---------------- sweep 2: cols [DD+HH, NN), all rows ----------------
__global__ void sweep2_part(const float* __restrict__ mu, const float* __restrict__ sig,
                            const float* __restrict__ eps)
{
    const int t = threadIdx.x;
    const int col = t & 7;
    const int lane = t >> 3;
    const int i0 = blockIdx.x * 257;
    const int j = DD + HH + col;
    float acc = 0.f;
    for (int r = lane; r < 257; r += 32) {
        int i = i0 + r;
        if (i < NN) {
            float vi = (i < DD) ? g_context[i] : g_vals1[i - DD];
            size_t off = (size_t)i * NN + j;
            acc += vi * (mu[off] + sig[off] * eps[off]);
        }
    }
    __shared__ float sh[256];
    sh[t] = acc;
    __syncthreads();
    for (int s = 128; s >= 8; s >>= 1) {
        if (t < s) sh[t] += sh[t + s];
        __syncthreads();
    }
    if (t < 8) g_s2_part[blockIdx.x * 8 + t] = sh[t];
}

__global__ void final_out(const float* __restrict__ bmu, const float* __restrict__ bsig,
                          const float* __restrict__ epsb, float* __restrict__ out)
{
    int t = threadIdx.x;
    if (t < OO) {
        float acc = 0.f;
        #pragma unroll
        for (int b = 0; b < 32; ++b) acc += g_s2_part[b * 8 + t];
        int j = DD + HH + t;
        float v = tanhf(acc + bmu[j] + bsig[j] * epsb[j]);
        out[t] = 1.0f / (1.0f + expf(-v));
    }
}

// ---------------- launcher -------------------------------------------------------
extern "C" void kernel_launch(void* const* d_in, const int* in_sizes, int n_in,
                              void* d_out, int out_size)
{
    const float* inp  = (const float*)d_in[0];
    const float* Wq   = (const float*)d_in[1];
    const float* bq   = (const float*)d_in[2];
    const float* Wk   = (const float*)d_in[3];
    const float* bk   = (const float*)d_in[4];
    const float* Wv   = (const float*)d_in[5];
    const float* bv   = (const float*)d_in[6];
    const float* wmu  = (const float*)d_in[7];
    const float* wsig = (const float*)d_in[8];
    const float* bmu  = (const float*)d_in[9];
    const float* bsig = (const float*)d_in[10];
    const float* epsw = (const float*)d_in[11];
    const float* epsb = (const float*)d_in[12];
    float* out = (float*)d_out;

    __nv_bfloat16 *ihi, *ilo, *wtqhi, *wtqlo, *wtkhi, *wtklo;
    __nv_bfloat16 *qhi, *qlo, *khi, *klo;
    float *sc;
    cudaGetSymbolAddress((void**)&ihi,   g_ihi);
    cudaGetSymbolAddress((void**)&ilo,   g_ilo);
    cudaGetSymbolAddress((void**)&wtqhi, g_wtqhi);
    cudaGetSymbolAddress((void**)&wtqlo, g_wtqlo);
    cudaGetSymbolAddress((void**)&wtkhi, g_wtkhi);
    cudaGetSymbolAddress((void**)&wtklo, g_wtklo);
    cudaGetSymbolAddress((void**)&qhi,   g_qhi);
    cudaGetSymbolAddress((void**)&qlo,   g_qlo);
    cudaGetSymbolAddress((void**)&khi,   g_khi);
    cudaGetSymbolAddress((void**)&klo,   g_klo);
    cudaGetSymbolAddress((void**)&sc,    g_scores);

    cudaFuncSetAttribute(tc_gemm, cudaFuncAttributeMaxDynamicSharedMemorySize,
                         SMEM_GEMM);

    const dim3 split_grid((KP + 255) / 256, MM);
    const dim3 tr_grid(WROWS / 32, KP / 32);
    const dim3 tr_blk(32, 8);
    const dim3 qk_grid(2 * (WROWS / 128), MM / 128);   // 124 x 16 (q & k fused)
    const dim3 sc_grid(MM / 128, MM / 128);            // 16 x 16

    // input split to bf16 hi/lo
    split_pad<<<split_grid, 256>>>(inp, ihi, ilo, DD);

    // transpose+split both weight matrices
    transpose_split<<<tr_grid, tr_blk>>>(Wq, wtqhi, wtqlo);
    transpose_split<<<tr_grid, tr_blk>>>(Wk, wtkhi, wtklo);

    // q = inp @ Wq + bq  AND  k = inp @ Wk + bk  (one launch, bf16 hi/lo out)
    tc_gemm<<<qk_grid, 128, SMEM_GEMM>>>(ihi, ilo,
                                         wtqhi, wtqlo, wtkhi, wtklo,
                                         bq, bk, WROWS / 128, 1.f,
                                         nullptr, 0, qhi, qlo, khi, klo);

    // scores = q @ k^T / sqrt(D)  (fp32 out)
    tc_gemm<<<sc_grid, 128, SMEM_GEMM>>>(qhi, qlo,
                                         khi, klo, nullptr, nullptr,
                                         nullptr, nullptr, 1 << 20,
                                         rsqrtf((float)DD),
                                         sc, MM, nullptr, nullptr, nullptr, nullptr);

    softmax_rows<<<MM, 256>>>(sc);

    colsum_part<<<dim3(MM / 256, 16), 256>>>(sc);
    colsum_reduce<<<MM / 256, 256>>>();

    // context = ((colsum/M) @ inp) @ Wv + bv
    u_part<<<dim3((DD + 255) / 256, 16), 256>>>(inp);
    u_reduce<<<(DD + 255) / 256, 256>>>();
    ctx2_part<<<dim3((DD + 255) / 256, 16), 256>>>(Wv);
    ctx2_reduce<<<(DD + 255) / 256, 256>>>(bv);

    sweep1_part<<<dim3(3, 61), 256>>>(wmu, wsig, epsw);
    sweep1_final<<<3, 256>>>(bmu, bsig, epsb);

    sweep2_part<<<32, 256>>>(wmu, wsig, epsw);
    final_out<<<1, 32>>>(bmu, bsig, epsb, out);
}

// round 10
// speedup vs baseline: 2.6222x; 1.0380x over previous
#include <cuda_runtime.h>
#include <cuda_bf16.h>
#include <cstdint>
#include <math.h>

// ---------------- problem constants ----------------
#define MM 2048      // num_memories
#define DD 7686      // input size
#define HH 512
#define OO 8
#define NN 8206      // DD + HH + OO
#define KP 7744      // K padded to multiple of 32
#define WROWS 7808   // padded B rows for W^T (61 * 128)
#define BKC 32
#define KCHUNKS (KP / BKC)   // 242

// ---------------- small PTX helpers ----------------
__device__ __forceinline__ uint32_t smem_to_u32(const void* p) {
    uint32_t a;
    asm("{ .reg .u64 t; cvta.to.shared.u64 t, %1; cvt.u32.u64 %0, t; }"
        : "=r"(a) : "l"(p));
    return a;
}

__device__ __forceinline__ void cpa16(uint32_t s, const void* g) {
    asm volatile("cp.async.cg.shared.global [%0], [%1], 16;" :: "r"(s), "l"(g) : "memory");
}
#define CP_COMMIT() asm volatile("cp.async.commit_group;" ::: "memory")

__device__ __forceinline__ void ldsm4(uint32_t (&r)[4], uint32_t addr) {
    asm volatile("ldmatrix.sync.aligned.m8n8.x4.shared.b16 {%0,%1,%2,%3}, [%4];"
                 : "=r"(r[0]), "=r"(r[1]), "=r"(r[2]), "=r"(r[3]) : "r"(addr));
}

__device__ __forceinline__ void mma16816(float (&d)[4], const uint32_t (&a)[4],
                                         const uint32_t b0, const uint32_t b1) {
    asm volatile(
        "mma.sync.aligned.m16n8k16.row.col.f32.bf16.bf16.f32 "
        "{%0,%1,%2,%3}, {%4,%5,%6,%7}, {%8,%9}, {%0,%1,%2,%3};"
        : "+f"(d[0]), "+f"(d[1]), "+f"(d[2]), "+f"(d[3])
        : "r"(a[0]), "r"(a[1]), "r"(a[2]), "r"(a[3]), "r"(b0), "r"(b1));
}

// SW64 swizzle for 64B-wide smem rows (conflict-free ldmatrix)
__device__ __forceinline__ uint32_t sw_off(int row, int c) {
    uint32_t o = (uint32_t)(row * 64 + c * 16);
    return o ^ ((o >> 3) & 0x30);
}

// ---------------- device scratch ----------------
__device__ __nv_bfloat16 g_ihi[(size_t)MM * KP];
__device__ __nv_bfloat16 g_ilo[(size_t)MM * KP];
__device__ __nv_bfloat16 g_wtqhi[(size_t)WROWS * KP];
__device__ __nv_bfloat16 g_wtqlo[(size_t)WROWS * KP];
__device__ __nv_bfloat16 g_wtkhi[(size_t)WROWS * KP];
__device__ __nv_bfloat16 g_wtklo[(size_t)WROWS * KP];
__device__ __nv_bfloat16 g_qhi[(size_t)MM * KP];
__device__ __nv_bfloat16 g_qlo[(size_t)MM * KP];
__device__ __nv_bfloat16 g_khi[(size_t)MM * KP];
__device__ __nv_bfloat16 g_klo[(size_t)MM * KP];
__device__ float g_scores[(size_t)MM * MM];
__device__ float g_cs_part[16 * MM];
__device__ float g_colsum[MM];
__device__ float g_part[16 * DD];
__device__ float g_u[DD];
__device__ float g_context[DD];
__device__ float g_s1_part[61 * (HH + OO)];
__device__ float g_vals1[HH + OO];
__device__ float g_s2_part[32 * OO];

// ---------------- split fp32 -> bf16 hi/lo, pad cols to KP ----------------
__global__ void split_pad(const float* __restrict__ x,
                          __nv_bfloat16* __restrict__ hi,
                          __nv_bfloat16* __restrict__ lo, int cols)
{
    int c = blockIdx.x * 256 + threadIdx.x;
    if (c >= KP) return;
    int r = blockIdx.y;
    float v = (c < cols) ? x[(size_t)r * cols + c] : 0.f;
    __nv_bfloat16 h = __float2bfloat16(v);
    float rem = v - __bfloat162float(h);
    hi[(size_t)r * KP + c] = h;
    lo[(size_t)r * KP + c] = __float2bfloat16(rem);
}

// ---------------- transpose + split: W[k][n] -> Wt[n][k] bf16 hi/lo -------------
__global__ void transpose_split(const float* __restrict__ W,
                                __nv_bfloat16* __restrict__ Thi,
                                __nv_bfloat16* __restrict__ Tlo)
{
    __shared__ float s[32][33];
    const int tx = threadIdx.x;
    const int ty = threadIdx.y;
    const int n0 = blockIdx.x * 32;
    const int k0 = blockIdx.y * 32;

    #pragma unroll
    for (int i = 0; i < 4; ++i) {
        int a = ty + 8 * i;
        int k = k0 + a;
        int n = n0 + tx;
        s[a][tx] = (k < DD && n < DD) ? W[(size_t)k * DD + n] : 0.f;
    }
    __syncthreads();
    #pragma unroll
    for (int i = 0; i < 4; ++i) {
        int a = ty + 8 * i;
        float v = s[tx][a];
        __nv_bfloat16 h = __float2bfloat16(v);
        float rem = v - __bfloat162float(h);
        size_t off = (size_t)(n0 + a) * KP + (k0 + tx);
        Thi[off] = h;
        Tlo[off] = __float2bfloat16(rem);
    }
}

// ---------------- bf16x3 mma.sync GEMM, CTA tile 128x128, 4 warps ---------------
// Dual-B dispatch (q & k fused). Term-major inner ordering: all accumulators
// receive hi*hi, then hi*lo, then lo*hi per k-slice -> no back-to-back RAW
// chains on any accumulator, tensor pipe issues stall-free. Per-accumulator
// operation sequence is unchanged => bit-identical results.
#define T_AHI 0
#define T_ALO 8192
#define T_BHI 16384
#define T_BLO 24576
#define STAGE_BYTES 32768
#define NSTAGE 3
#define SMEM_GEMM (NSTAGE * STAGE_BYTES)   // 98304

__global__ __launch_bounds__(128, 2)
void tc_gemm(const __nv_bfloat16* __restrict__ Ahi, const __nv_bfloat16* __restrict__ Alo,
             const __nv_bfloat16* __restrict__ B1hi, const __nv_bfloat16* __restrict__ B1lo,
             const __nv_bfloat16* __restrict__ B2hi, const __nv_bfloat16* __restrict__ B2lo,
             const float* __restrict__ bias1, const float* __restrict__ bias2,
             int nsplit, float scale,
             float* __restrict__ Cf, int Cld,
             __nv_bfloat16* __restrict__ C1hi, __nv_bfloat16* __restrict__ C1lo,
             __nv_bfloat16* __restrict__ C2hi, __nv_bfloat16* __restrict__ C2lo)
{
    extern __shared__ char smem[];
    const uint32_t sb = smem_to_u32(smem);
    const int t   = threadIdx.x;
    const int wid = t >> 5;
    const int lid = t & 31;
    const int m0 = blockIdx.y * 128;

    const __nv_bfloat16 *Bhi, *Blo;
    const float* bias;
    __nv_bfloat16 *Chi, *Clo;
    int n0;
    if ((int)blockIdx.x < nsplit) {
        n0 = blockIdx.x * 128;
        Bhi = B1hi; Blo = B1lo; bias = bias1; Chi = C1hi; Clo = C1lo;
    } else {
        n0 = (blockIdx.x - nsplit) * 128;
        Bhi = B2hi; Blo = B2lo; bias = bias2; Chi = C2hi; Clo = C2lo;
    }

    const int rl = t >> 2;
    const int cl = t & 3;
    const uint32_t soR[4] = { sw_off(rl, cl), sw_off(rl + 32, cl),
                              sw_off(rl + 64, cl), sw_off(rl + 96, cl) };

    float acc[4][8][4];
    #pragma unroll
    for (int a = 0; a < 4; ++a)
        #pragma unroll
        for (int b = 0; b < 8; ++b)
            #pragma unroll
            for (int c = 0; c < 4; ++c) acc[a][b][c] = 0.f;

    const char* pAhi = (const char*)Ahi;
    const char* pAlo = (const char*)Alo;
    const char* pBhi = (const char*)Bhi;
    const char* pBlo = (const char*)Blo;

    auto load_stage = [&](int kc, int slot) {
        const int k0 = kc * BKC;
        const uint32_t st = sb + slot * STAGE_BYTES;
        #pragma unroll
        for (int i = 0; i < 4; ++i) {
            const int r = rl + 32 * i;
            size_t ga = (((size_t)(m0 + r) * KP + k0 + cl * 8) << 1);
            size_t gb = (((size_t)(n0 + r) * KP + k0 + cl * 8) << 1);
            cpa16(st + T_AHI + soR[i], pAhi + ga);
            cpa16(st + T_ALO + soR[i], pAlo + ga);
            cpa16(st + T_BHI + soR[i], pBhi + gb);
            cpa16(st + T_BLO + soR[i], pBlo + gb);
        }
        CP_COMMIT();
    };

    const int wm = wid >> 1;       // 0..1 (m offset 64)
    const int wn = wid & 1;        // 0..1 (n offset 64)
    const int lrow = lid & 15;
    const int lcg  = lid >> 4;     // 0..1

    load_stage(0, 0);
    load_stage(1, 1);

    int slot = 0;                  // kc % 3
    int nslot = 2;                 // (kc+2) % 3
    for (int kc = 0; kc < KCHUNKS; ++kc) {
        asm volatile("cp.async.wait_group 1;" ::: "memory");
        __syncthreads();
        if (kc + 2 < KCHUNKS) load_stage(kc + 2, nslot);
        else CP_COMMIT();

        const uint32_t st = sb + slot * STAGE_BYTES;
        slot = (slot == 2) ? 0 : slot + 1;
        nslot = (nslot == 2) ? 0 : nslot + 1;

        #pragma unroll
        for (int ks = 0; ks < 2; ++ks) {
            const int ccol = ks * 2 + lcg;
            uint32_t ahi[4][4], alo[4][4];
            #pragma unroll
            for (int mt = 0; mt < 4; ++mt) {
                uint32_t so = sw_off(wm * 64 + mt * 16 + lrow, ccol);
                ldsm4(ahi[mt], st + T_AHI + so);
                ldsm4(alo[mt], st + T_ALO + so);
            }
            uint32_t bhi[8][2], blo[8][2];
            #pragma unroll
            for (int p = 0; p < 4; ++p) {
                uint32_t so = sw_off(wn * 64 + p * 16 + lrow, ccol);
                uint32_t r[4];
                ldsm4(r, st + T_BHI + so);
                bhi[2*p][0] = r[0]; bhi[2*p][1] = r[2];
                bhi[2*p+1][0] = r[1]; bhi[2*p+1][1] = r[3];
                ldsm4(r, st + T_BLO + so);
                blo[2*p][0] = r[0]; blo[2*p][1] = r[2];
                blo[2*p+1][0] = r[1]; blo[2*p+1][1] = r[3];
            }
            // ---- term-major: 32 independent accumulators between reuses ----
            #pragma unroll
            for (int mt = 0; mt < 4; ++mt)
                #pragma unroll
                for (int q = 0; q < 8; ++q)
                    mma16816(acc[mt][q], ahi[mt], bhi[q][0], bhi[q][1]);
            #pragma unroll
            for (int mt = 0; mt < 4; ++mt)
                #pragma unroll
                for (int q = 0; q < 8; ++q)
                    mma16816(acc[mt][q], ahi[mt], blo[q][0], blo[q][1]);
            #pragma unroll
            for (int mt = 0; mt < 4; ++mt)
                #pragma unroll
                for (int q = 0; q < 8; ++q)
                    mma16816(acc[mt][q], alo[mt], bhi[q][0], bhi[q][1]);
        }
    }

    // ---- epilogue ----
    const int g  = lid >> 2;
    const int t4 = lid & 3;
    #pragma unroll
    for (int mt = 0; mt < 4; ++mt) {
        #pragma unroll
        for (int nt = 0; nt < 8; ++nt) {
            const int m = m0 + wm * 64 + mt * 16 + g;
            const int n = n0 + wn * 64 + nt * 8 + t4 * 2;
            float d0 = acc[mt][nt][0], d1 = acc[mt][nt][1];
            float d2 = acc[mt][nt][2], d3 = acc[mt][nt][3];
            if (Cf) {
                if (n + 1 < Cld) {
                    float2 v0 = make_float2(d0 * scale, d1 * scale);
                    float2 v1 = make_float2(d2 * scale, d3 * scale);
                    *(float2*)(Cf + (size_t)m * Cld + n) = v0;
                    *(float2*)(Cf + (size_t)(m + 8) * Cld + n) = v1;
                }
            } else {
                if (n < KP) {
                    float b0 = (n     < DD) ? bias[n]     : 0.f;
                    float b1 = (n + 1 < DD) ? bias[n + 1] : 0.f;
                    float v0 = (n     < DD) ? d0 + b0 : 0.f;
                    float v1 = (n + 1 < DD) ? d1 + b1 : 0.f;
                    float v2 = (n     < DD) ? d2 + b0 : 0.f;
                    float v3 = (n + 1 < DD) ? d3 + b1 : 0.f;
                    __nv_bfloat16 h0 = __float2bfloat16(v0);
                    __nv_bfloat16 h1 = __float2bfloat16(v1);
                    __nv_bfloat16 h2 = __float2bfloat16(v2);
                    __nv_bfloat16 h3 = __float2bfloat16(v3);
                    __nv_bfloat162 hp0; hp0.x = h0; hp0.y = h1;
                    __nv_bfloat162 hp1; hp1.x = h2; hp1.y = h3;
                    __nv_bfloat162 lp0;
                    lp0.x = __float2bfloat16(v0 - __bfloat162float(h0));
                    lp0.y = __float2bfloat16(v1 - __bfloat162float(h1));
                    __nv_bfloat162 lp1;
                    lp1.x = __float2bfloat16(v2 - __bfloat162float(h2));
                    lp1.y = __float2bfloat16(v3 - __bfloat162float(h3));
                    *(__nv_bfloat162*)(Chi + (size_t)m * KP + n) = hp0;
                    *(__nv_bfloat162*)(Chi + (size_t)(m + 8) * KP + n) = hp1;
                    *(__nv_bfloat162*)(Clo + (size_t)m * KP + n) = lp0;
                    *(__nv_bfloat162*)(Clo + (size_t)(m + 8) * KP + n) = lp1;
                }
            }
        }
    }
}

// ---------------- row softmax (in place), row length MM ------------------------
__global__ void softmax_rows(float* __restrict__ S)
{
    const int row = blockIdx.x;
    const int t = threadIdx.x;
    float* r = S + (size_t)row * MM;
    float v[8];
    #pragma unroll
    for (int i = 0; i < 8; ++i) v[i] = r[i * 256 + t];

    float mx = v[0];
    #pragma unroll
    for (int i = 1; i < 8; ++i) mx = fmaxf(mx, v[i]);

    __shared__ float sh[32];
    #pragma unroll
    for (int o = 16; o > 0; o >>= 1) mx = fmaxf(mx, __shfl_xor_sync(0xffffffff, mx, o));
    if ((t & 31) == 0) sh[t >> 5] = mx;
    __syncthreads();
    if (t < 32) {
        float m = (t < 8) ? sh[t] : -INFINITY;
        #pragma unroll
        for (int o = 4; o > 0; o >>= 1) m = fmaxf(m, __shfl_xor_sync(0xffffffff, m, o));
        sh[0] = m;
    }
    __syncthreads();
    mx = sh[0];
    __syncthreads();

    float sum = 0.f;
    #pragma unroll
    for (int i = 0; i < 8; ++i) { v[i] = expf(v[i] - mx); sum += v[i]; }
    #pragma unroll
    for (int o = 16; o > 0; o >>= 1) sum += __shfl_xor_sync(0xffffffff, sum, o);
    if ((t & 31) == 0) sh[t >> 5] = sum;
    __syncthreads();
    if (t < 32) {
        float s = (t < 8) ? sh[t] : 0.f;
        #pragma unroll
        for (int o = 4; o > 0; o >>= 1) s += __shfl_xor_sync(0xffffffff, s, o);
        sh[0] = s;
    }
    __syncthreads();
    float inv = 1.f / sh[0];
    #pragma unroll
    for (int i = 0; i < 8; ++i) r[i * 256 + t] = v[i] * inv;
}

// ---------------- column sums of P ----------------
__global__ void colsum_part(const float* __restrict__ P)
{
    int j = blockIdx.x * 256 + threadIdx.x;
    int r0 = blockIdx.y * 128;
    float acc = 0.f;
    for (int r = 0; r < 128; ++r) acc += P[(size_t)(r0 + r) * MM + j];
    g_cs_part[blockIdx.y * MM + j] = acc;
}

__global__ void colsum_reduce()
{
    int j = blockIdx.x * 256 + threadIdx.x;
    float acc = 0.f;
    #pragma unroll
    for (int c = 0; c < 16; ++c) acc += g_cs_part[c * MM + j];
    g_colsum[j] = acc;
}

// ---------------- u = (colsum @ inp) / M ----------------
__global__ void u_part(const float* __restrict__ X)
{
    int j = blockIdx.x * 256 + threadIdx.x;
    if (j >= DD) return;
    int r0 = blockIdx.y * 128;
    float acc = 0.f;
    for (int r = 0; r < 128; ++r) {
        int l = r0 + r;
        acc += g_colsum[l] * X[(size_t)l * DD + j];
    }
    g_part[blockIdx.y * DD + j] = acc;
}

__global__ void u_reduce()
{
    int j = blockIdx.x * 256 + threadIdx.x;
    if (j >= DD) return;
    float acc = 0.f;
    #pragma unroll
    for (int c = 0; c < 16; ++c) acc += g_part[c * DD + j];
    g_u[j] = acc * (1.0f / (float)MM);
}

// ---------------- context = u @ Wv + bv ----------------
__global__ void ctx2_part(const float* __restrict__ Wv)
{
    int j = blockIdx.x * 256 + threadIdx.x;
    if (j >= DD) return;
    int i0 = blockIdx.y * 481;
    float acc = 0.f;
    for (int r = 0; r < 481; ++r) {
        int i = i0 + r;
        if (i < DD) acc += g_u[i] * Wv[(size_t)i * DD + j];
    }
    g_part[blockIdx.y * DD + j] = acc;
}

__global__ void ctx2_reduce(const float* __restrict__ bv)
{
    int j = blockIdx.x * 256 + threadIdx.x;
    if (j >= DD) return;
    float acc = 0.f;
    #pragma unroll
    for (int c = 0; c < 16; ++c) acc += g_part[c * DD + j];
    g_context[j] = acc + bv[j];
}

// ---------------- sweep 1: cols [DD, NN), rows i<DD ----------------
__global__ void sweep1_part(const float* __restrict__ mu, const float* __restrict__ sig,
                            const float* __restrict__ eps)
{
    int jj = blockIdx.x * 256 + threadIdx.x;
    if (jj >= HH + OO) return;
    int j = DD + jj;
    int i0 = blockIdx.y * 126;
    float acc = 0.f;
    for (int r = 0; r < 126; ++r) {
        int i = i0 + r;
        size_t off = (size_t)i * NN + j;
        acc += g_context[i] * (mu[off] + sig[off] * eps[off]);
    }
    g_s1_part[blockIdx.y * (HH + OO) + jj] = acc;
}

__global__ void sweep1_final(const float* __restrict__ bmu, const float* __restrict__ bsig,
                             const float* __restrict__ epsb)
{
    int jj = blockIdx.x * 256 + threadIdx.x;
    if (jj >= HH + OO) return;
    int j = DD + jj;
    float acc = 0.f;
    for (int c = 0; c < 61; ++c) acc += g_s1_part[c * (HH + OO) + jj];
    g_vals1[jj] = tanhf(acc + bmu[j] + bsig[j] * epsb[j]);
}

// ---------------- sweep 2: cols [DD+HH, NN), all rows ----------------
__global__ void sweep2_part(const float* __restrict__ mu, const float* __restrict__ sig,
                            const float* __restrict__ eps)
{
    const int t = threadIdx.x;
    const int col = t & 7;
    const int lane = t >> 3;
    const int i0 = blockIdx.x * 257;
    const int j = DD + HH + col;
    float acc = 0.f;
    for (int r = lane; r < 257; r += 32) {
        int i = i0 + r;
        if (i < NN) {
            float vi = (i < DD) ? g_context[i] : g_vals1[i - DD];
            size_t off = (size_t)i * NN + j;
            acc += vi * (mu[off] + sig[off] * eps[off]);
        }
    }
    __shared__ float sh[256];
    sh[t] = acc;
    __syncthreads();
    for (int s = 128; s >= 8; s >>= 1) {
        if (t < s) sh[t] += sh[t + s];
        __syncthreads();
    }
    if (t < 8) g_s2_part[blockIdx.x * 8 + t] = sh[t];
}

__global__ void final_out(const float* __restrict__ bmu, const float* __restrict__ bsig,
                          const float* __restrict__ epsb, float* __restrict__ out)
{
    int t = threadIdx.x;
    if (t < OO) {
        float acc = 0.f;
        #pragma unroll
        for (int b = 0; b < 32; ++b) acc += g_s2_part[b * 8 + t];
        int j = DD + HH + t;
        float v = tanhf(acc + bmu[j] + bsig[j] * epsb[j]);
        out[t] = 1.0f / (1.0f + expf(-v));
    }
}

// ---------------- launcher -------------------------------------------------------
extern "C" void kernel_launch(void* const* d_in, const int* in_sizes, int n_in,
                              void* d_out, int out_size)
{
    const float* inp  = (const float*)d_in[0];
    const float* Wq   = (const float*)d_in[1];
    const float* bq   = (const float*)d_in[2];
    const float* Wk   = (const float*)d_in[3];
    const float* bk   = (const float*)d_in[4];
    const float* Wv   = (const float*)d_in[5];
    const float* bv   = (const float*)d_in[6];
    const float* wmu  = (const float*)d_in[7];
    const float* wsig = (const float*)d_in[8];
    const float* bmu  = (const float*)d_in[9];
    const float* bsig = (const float*)d_in[10];
    const float* epsw = (const float*)d_in[11];
    const float* epsb = (const float*)d_in[12];
    float* out = (float*)d_out;

    __nv_bfloat16 *ihi, *ilo, *wtqhi, *wtqlo, *wtkhi, *wtklo;
    __nv_bfloat16 *qhi, *qlo, *khi, *klo;
    float *sc;
    cudaGetSymbolAddress((void**)&ihi,   g_ihi);
    cudaGetSymbolAddress((void**)&ilo,   g_ilo);
    cudaGetSymbolAddress((void**)&wtqhi, g_wtqhi);
    cudaGetSymbolAddress((void**)&wtqlo, g_wtqlo);
    cudaGetSymbolAddress((void**)&wtkhi, g_wtkhi);
    cudaGetSymbolAddress((void**)&wtklo, g_wtklo);
    cudaGetSymbolAddress((void**)&qhi,   g_qhi);
    cudaGetSymbolAddress((void**)&qlo,   g_qlo);
    cudaGetSymbolAddress((void**)&khi,   g_khi);
    cudaGetSymbolAddress((void**)&klo,   g_klo);
    cudaGetSymbolAddress((void**)&sc,    g_scores);

    cudaFuncSetAttribute(tc_gemm, cudaFuncAttributeMaxDynamicSharedMemorySize,
                         SMEM_GEMM);

    const dim3 split_grid((KP + 255) / 256, MM);
    const dim3 tr_grid(WROWS / 32, KP / 32);
    const dim3 tr_blk(32, 8);
    const dim3 qk_grid(2 * (WROWS / 128), MM / 128);   // 122 x 16 (q & k fused)
    const dim3 sc_grid(MM / 128, MM / 128);            // 16 x 16

    // input split to bf16 hi/lo
    split_pad<<<split_grid, 256>>>(inp, ihi, ilo, DD);

    // transpose+split both weight matrices
    transpose_split<<<tr_grid, tr_blk>>>(Wq, wtqhi, wtqlo);
    transpose_split<<<tr_grid, tr_blk>>>(Wk, wtkhi, wtklo);

    // q = inp @ Wq + bq  AND  k = inp @ Wk + bk  (one launch, bf16 hi/lo out)
    tc_gemm<<<qk_grid, 128, SMEM_GEMM>>>(ihi, ilo,
                                         wtqhi, wtqlo, wtkhi, wtklo,
                                         bq, bk, WROWS / 128, 1.f,
                                         nullptr, 0, qhi, qlo, khi, klo);

    // scores = q @ k^T / sqrt(D)  (fp32 out)
    tc_gemm<<<sc_grid, 128, SMEM_GEMM>>>(qhi, qlo,
                                         khi, klo, nullptr, nullptr,
                                         nullptr, nullptr, 1 << 20,
                                         rsqrtf((float)DD),
                                         sc, MM, nullptr, nullptr, nullptr, nullptr);

    softmax_rows<<<MM, 256>>>(sc);

    colsum_part<<<dim3(MM / 256, 16), 256>>>(sc);
    colsum_reduce<<<MM / 256, 256>>>();

    // context = ((colsum/M) @ inp) @ Wv + bv
    u_part<<<dim3((DD + 255) / 256, 16), 256>>>(inp);
    u_reduce<<<(DD + 255) / 256, 256>>>();
    ctx2_part<<<dim3((DD + 255) / 256, 16), 256>>>(Wv);
    ctx2_reduce<<<(DD + 255) / 256, 256>>>(bv);

    sweep1_part<<<dim3(3, 61), 256>>>(wmu, wsig, epsw);
    sweep1_final<<<3, 256>>>(bmu, bsig, epsb);

    sweep2_part<<<32, 256>>>(wmu, wsig, epsw);
    final_out<<<1, 32>>>(bmu, bsig, epsb, out);
}

// round 11
// speedup vs baseline: 2.6829x; 1.0232x over previous
#include <cuda_runtime.h>
#include <cuda_bf16.h>
#include <cstdint>
#include <math.h>

// ---------------- problem constants ----------------
#define MM 2048      // num_memories
#define DD 7686      // input size
#define HH 512
#define OO 8
#define NN 8206      // DD + HH + OO
#define KP 7744      // K padded to multiple of 32
#define WROWS 7808   // padded B rows for W^T (61 * 128)
#define BKC 32
#define KCHUNKS (KP / BKC)   // 242

// ---------------- small PTX helpers ----------------
__device__ __forceinline__ uint32_t smem_to_u32(const void* p) {
    uint32_t a;
    asm("{ .reg .u64 t; cvta.to.shared.u64 t, %1; cvt.u32.u64 %0, t; }"
        : "=r"(a) : "l"(p));
    return a;
}

__device__ __forceinline__ void cpa16(uint32_t s, const void* g) {
    asm volatile("cp.async.cg.shared.global [%0], [%1], 16;" :: "r"(s), "l"(g) : "memory");
}
#define CP_COMMIT() asm volatile("cp.async.commit_group;" ::: "memory")

__device__ __forceinline__ void ldsm4(uint32_t (&r)[4], uint32_t addr) {
    asm volatile("ldmatrix.sync.aligned.m8n8.x4.shared.b16 {%0,%1,%2,%3}, [%4];"
                 : "=r"(r[0]), "=r"(r[1]), "=r"(r[2]), "=r"(r[3]) : "r"(addr));
}

__device__ __forceinline__ void mma16816(float (&d)[4], const uint32_t (&a)[4],
                                         const uint32_t b0, const uint32_t b1) {
    asm volatile(
        "mma.sync.aligned.m16n8k16.row.col.f32.bf16.bf16.f32 "
        "{%0,%1,%2,%3}, {%4,%5,%6,%7}, {%8,%9}, {%0,%1,%2,%3};"
        : "+f"(d[0]), "+f"(d[1]), "+f"(d[2]), "+f"(d[3])
        : "r"(a[0]), "r"(a[1]), "r"(a[2]), "r"(a[3]), "r"(b0), "r"(b1));
}

// SW64 swizzle for 64B-wide smem rows (conflict-free ldmatrix)
__device__ __forceinline__ uint32_t sw_off(int row, int c) {
    uint32_t o = (uint32_t)(row * 64 + c * 16);
    return o ^ ((o >> 3) & 0x30);
}

// ---------------- device scratch ----------------
__device__ __nv_bfloat16 g_ihi[(size_t)MM * KP];
__device__ __nv_bfloat16 g_ilo[(size_t)MM * KP];
__device__ __nv_bfloat16 g_wtqhi[(size_t)WROWS * KP];
__device__ __nv_bfloat16 g_wtqlo[(size_t)WROWS * KP];
__device__ __nv_bfloat16 g_wtkhi[(size_t)WROWS * KP];
__device__ __nv_bfloat16 g_wtklo[(size_t)WROWS * KP];
__device__ __nv_bfloat16 g_qhi[(size_t)MM * KP];
__device__ __nv_bfloat16 g_qlo[(size_t)MM * KP];
__device__ __nv_bfloat16 g_khi[(size_t)MM * KP];
__device__ __nv_bfloat16 g_klo[(size_t)MM * KP];
__device__ float g_scores[(size_t)MM * MM];
__device__ float g_cs_part[16 * MM];
__device__ float g_colsum[MM];
__device__ float g_part[16 * DD];
__device__ float g_u[DD];
__device__ float g_context[DD];
__device__ float g_s1_part[61 * (HH + OO)];
__device__ float g_vals1[HH + OO];
__device__ float g_s2_part[32 * OO];

// ---------------- split fp32 -> bf16 hi/lo, pad cols to KP (8B stores) ----------
__global__ void split_pad(const float* __restrict__ x,
                          __nv_bfloat16* __restrict__ hi,
                          __nv_bfloat16* __restrict__ lo, int cols)
{
    int c = (blockIdx.x * 256 + threadIdx.x) * 4;
    if (c >= KP) return;
    int r = blockIdx.y;
    const float* xr = x + (size_t)r * cols;
    uint32_t hw[2], lw[2];
    #pragma unroll
    for (int j = 0; j < 2; ++j) {
        float v0 = (c + 2*j     < cols) ? xr[c + 2*j]     : 0.f;
        float v1 = (c + 2*j + 1 < cols) ? xr[c + 2*j + 1] : 0.f;
        __nv_bfloat16 h0 = __float2bfloat16(v0);
        __nv_bfloat16 h1 = __float2bfloat16(v1);
        __nv_bfloat162 hp; hp.x = h0; hp.y = h1;
        __nv_bfloat162 lp;
        lp.x = __float2bfloat16(v0 - __bfloat162float(h0));
        lp.y = __float2bfloat16(v1 - __bfloat162float(h1));
        hw[j] = *(uint32_t*)&hp;
        lw[j] = *(uint32_t*)&lp;
    }
    *(uint2*)(hi + (size_t)r * KP + c) = make_uint2(hw[0], hw[1]);
    *(uint2*)(lo + (size_t)r * KP + c) = make_uint2(lw[0], lw[1]);
}

// ---------------- transpose + split: W[k][n] -> Wt[n][k] bf16 hi/lo -------------
// 32x32 tile, 256 threads, 8B vector stores along k.
__global__ void transpose_split(const float* __restrict__ W,
                                __nv_bfloat16* __restrict__ Thi,
                                __nv_bfloat16* __restrict__ Tlo)
{
    __shared__ float s[32][33];
    const int t = threadIdx.x;
    const int n0 = blockIdx.x * 32;
    const int k0 = blockIdx.y * 32;

    #pragma unroll
    for (int i = 0; i < 4; ++i) {
        int idx = i * 256 + t;
        int kl = idx >> 5, nl = idx & 31;
        int k = k0 + kl, n = n0 + nl;
        s[kl][nl] = (k < DD && n < DD) ? W[(size_t)k * DD + n] : 0.f;
    }
    __syncthreads();

    const int a = t >> 3;          // n-local 0..31
    const int g = (t & 7) * 4;     // k-group
    uint32_t hw[2], lw[2];
    #pragma unroll
    for (int j = 0; j < 2; ++j) {
        float v0 = s[g + 2*j][a];
        float v1 = s[g + 2*j + 1][a];
        __nv_bfloat16 h0 = __float2bfloat16(v0);
        __nv_bfloat16 h1 = __float2bfloat16(v1);
        __nv_bfloat162 hp; hp.x = h0; hp.y = h1;
        __nv_bfloat162 lp;
        lp.x = __float2bfloat16(v0 - __bfloat162float(h0));
        lp.y = __float2bfloat16(v1 - __bfloat162float(h1));
        hw[j] = *(uint32_t*)&hp;
        lw[j] = *(uint32_t*)&lp;
    }
    size_t off = (size_t)(n0 + a) * KP + (k0 + g);
    *(uint2*)(Thi + off) = make_uint2(hw[0], hw[1]);
    *(uint2*)(Tlo + off) = make_uint2(lw[0], lw[1]);
}

// ---------------- bf16x3 mma.sync GEMM, CTA tile 128x128, 4 warps ---------------
// Dual-B dispatch (q & k fused). Term-major passes with fragment ldsm
// interleaved INTO the mma stream: only ahi+first bhi pair precede mma;
// remaining bhi/blo load under pass 1, alo under pass 2. Per-accumulator
// operation sequence unchanged => bit-identical results.
#define T_AHI 0
#define T_ALO 8192
#define T_BHI 16384
#define T_BLO 24576
#define STAGE_BYTES 32768
#define NSTAGE 3
#define SMEM_GEMM (NSTAGE * STAGE_BYTES)   // 98304

__global__ __launch_bounds__(128, 2)
void tc_gemm(const __nv_bfloat16* __restrict__ Ahi, const __nv_bfloat16* __restrict__ Alo,
             const __nv_bfloat16* __restrict__ B1hi, const __nv_bfloat16* __restrict__ B1lo,
             const __nv_bfloat16* __restrict__ B2hi, const __nv_bfloat16* __restrict__ B2lo,
             const float* __restrict__ bias1, const float* __restrict__ bias2,
             int nsplit, float scale,
             float* __restrict__ Cf, int Cld,
             __nv_bfloat16* __restrict__ C1hi, __nv_bfloat16* __restrict__ C1lo,
             __nv_bfloat16* __restrict__ C2hi, __nv_bfloat16* __restrict__ C2lo)
{
    extern __shared__ char smem[];
    const uint32_t sb = smem_to_u32(smem);
    const int t   = threadIdx.x;
    const int wid = t >> 5;
    const int lid = t & 31;
    const int m0 = blockIdx.y * 128;

    const __nv_bfloat16 *Bhi, *Blo;
    const float* bias;
    __nv_bfloat16 *Chi, *Clo;
    int n0;
    if ((int)blockIdx.x < nsplit) {
        n0 = blockIdx.x * 128;
        Bhi = B1hi; Blo = B1lo; bias = bias1; Chi = C1hi; Clo = C1lo;
    } else {
        n0 = (blockIdx.x - nsplit) * 128;
        Bhi = B2hi; Blo = B2lo; bias = bias2; Chi = C2hi; Clo = C2lo;
    }

    const int rl = t >> 2;
    const int cl = t & 3;
    const uint32_t soR[4] = { sw_off(rl, cl), sw_off(rl + 32, cl),
                              sw_off(rl + 64, cl), sw_off(rl + 96, cl) };

    float acc[4][8][4];
    #pragma unroll
    for (int a = 0; a < 4; ++a)
        #pragma unroll
        for (int b = 0; b < 8; ++b)
            #pragma unroll
            for (int c = 0; c < 4; ++c) acc[a][b][c] = 0.f;

    const char* pAhi = (const char*)Ahi;
    const char* pAlo = (const char*)Alo;
    const char* pBhi = (const char*)Bhi;
    const char* pBlo = (const char*)Blo;

    auto load_stage = [&](int kc, int slot) {
        const int k0 = kc * BKC;
        const uint32_t st = sb + slot * STAGE_BYTES;
        #pragma unroll
        for (int i = 0; i < 4; ++i) {
            const int r = rl + 32 * i;
            size_t ga = (((size_t)(m0 + r) * KP + k0 + cl * 8) << 1);
            size_t gb = (((size_t)(n0 + r) * KP + k0 + cl * 8) << 1);
            cpa16(st + T_AHI + soR[i], pAhi + ga);
            cpa16(st + T_ALO + soR[i], pAlo + ga);
            cpa16(st + T_BHI + soR[i], pBhi + gb);
            cpa16(st + T_BLO + soR[i], pBlo + gb);
        }
        CP_COMMIT();
    };

    const int wm = wid >> 1;       // 0..1 (m offset 64)
    const int wn = wid & 1;        // 0..1 (n offset 64)
    const int lrow = lid & 15;
    const int lcg  = lid >> 4;     // 0..1

    load_stage(0, 0);
    load_stage(1, 1);

    int slot = 0;                  // kc % 3
    int nslot = 2;                 // (kc+2) % 3
    for (int kc = 0; kc < KCHUNKS; ++kc) {
        asm volatile("cp.async.wait_group 1;" ::: "memory");
        __syncthreads();
        if (kc + 2 < KCHUNKS) load_stage(kc + 2, nslot);
        else CP_COMMIT();

        const uint32_t st = sb + slot * STAGE_BYTES;
        slot = (slot == 2) ? 0 : slot + 1;
        nslot = (nslot == 2) ? 0 : nslot + 1;

        #pragma unroll
        for (int ks = 0; ks < 2; ++ks) {
            const int ccol = ks * 2 + lcg;
            uint32_t ahi[4][4], alo[4][4];
            uint32_t bhi[8][2], blo[8][2];

            // minimal preload: A-hi fragments + first B-hi pair
            #pragma unroll
            for (int mt = 0; mt < 4; ++mt)
                ldsm4(ahi[mt], st + T_AHI + sw_off(wm * 64 + mt * 16 + lrow, ccol));
            {
                uint32_t r[4];
                ldsm4(r, st + T_BHI + sw_off(wn * 64 + lrow, ccol));
                bhi[0][0] = r[0]; bhi[0][1] = r[2];
                bhi[1][0] = r[1]; bhi[1][1] = r[3];
            }

            // pass 1: hi*hi  (prefetch remaining bhi + all blo under mma)
            #pragma unroll
            for (int p = 0; p < 4; ++p) {
                if (p < 3) {
                    uint32_t r[4];
                    ldsm4(r, st + T_BHI + sw_off(wn * 64 + (p + 1) * 16 + lrow, ccol));
                    bhi[2*p+2][0] = r[0]; bhi[2*p+2][1] = r[2];
                    bhi[2*p+3][0] = r[1]; bhi[2*p+3][1] = r[3];
                }
                {
                    uint32_t r[4];
                    ldsm4(r, st + T_BLO + sw_off(wn * 64 + p * 16 + lrow, ccol));
                    blo[2*p][0] = r[0]; blo[2*p][1] = r[2];
                    blo[2*p+1][0] = r[1]; blo[2*p+1][1] = r[3];
                }
                #pragma unroll
                for (int mt = 0; mt < 4; ++mt) {
                    mma16816(acc[mt][2*p],     ahi[mt], bhi[2*p][0],   bhi[2*p][1]);
                    mma16816(acc[mt][2*p + 1], ahi[mt], bhi[2*p+1][0], bhi[2*p+1][1]);
                }
            }

            // pass 2: hi*lo  (prefetch alo under mma)
            #pragma unroll
            for (int p = 0; p < 4; ++p) {
                ldsm4(alo[p], st + T_ALO + sw_off(wm * 64 + p * 16 + lrow, ccol));
                #pragma unroll
                for (int mt = 0; mt < 4; ++mt) {
                    mma16816(acc[mt][2*p],     ahi[mt], blo[2*p][0],   blo[2*p][1]);
                    mma16816(acc[mt][2*p + 1], ahi[mt], blo[2*p+1][0], blo[2*p+1][1]);
                }
            }

            // pass 3: lo*hi
            #pragma unroll
            for (int mt = 0; mt < 4; ++mt)
                #pragma unroll
                for (int q = 0; q < 8; ++q)
                    mma16816(acc[mt][q], alo[mt], bhi[q][0], bhi[q][1]);
        }
    }

    // ---- epilogue ----
    const int g  = lid >> 2;
    const int t4 = lid & 3;
    #pragma unroll
    for (int mt = 0; mt < 4; ++mt) {
        #pragma unroll
        for (int nt = 0; nt < 8; ++nt) {
            const int m = m0 + wm * 64 + mt * 16 + g;
            const int n = n0 + wn * 64 + nt * 8 + t4 * 2;
            float d0 = acc[mt][nt][0], d1 = acc[mt][nt][1];
            float d2 = acc[mt][nt][2], d3 = acc[mt][nt][3];
            if (Cf) {
                if (n + 1 < Cld) {
                    float2 v0 = make_float2(d0 * scale, d1 * scale);
                    float2 v1 = make_float2(d2 * scale, d3 * scale);
                    *(float2*)(Cf + (size_t)m * Cld + n) = v0;
                    *(float2*)(Cf + (size_t)(m + 8) * Cld + n) = v1;
                }
            } else {
                if (n < KP) {
                    float b0 = (n     < DD) ? bias[n]     : 0.f;
                    float b1 = (n + 1 < DD) ? bias[n + 1] : 0.f;
                    float v0 = (n     < DD) ? d0 + b0 : 0.f;
                    float v1 = (n + 1 < DD) ? d1 + b1 : 0.f;
                    float v2 = (n     < DD) ? d2 + b0 : 0.f;
                    float v3 = (n + 1 < DD) ? d3 + b1 : 0.f;
                    __nv_bfloat16 h0 = __float2bfloat16(v0);
                    __nv_bfloat16 h1 = __float2bfloat16(v1);
                    __nv_bfloat16 h2 = __float2bfloat16(v2);
                    __nv_bfloat16 h3 = __float2bfloat16(v3);
                    __nv_bfloat162 hp0; hp0.x = h0; hp0.y = h1;
                    __nv_bfloat162 hp1; hp1.x = h2; hp1.y = h3;
                    __nv_bfloat162 lp0;
                    lp0.x = __float2bfloat16(v0 - __bfloat162float(h0));
                    lp0.y = __float2bfloat16(v1 - __bfloat162float(h1));
                    __nv_bfloat162 lp1;
                    lp1.x = __float2bfloat16(v2 - __bfloat162float(h2));
                    lp1.y = __float2bfloat16(v3 - __bfloat162float(h3));
                    *(__nv_bfloat162*)(Chi + (size_t)m * KP + n) = hp0;
                    *(__nv_bfloat162*)(Chi + (size_t)(m + 8) * KP + n) = hp1;
                    *(__nv_bfloat162*)(Clo + (size_t)m * KP + n) = lp0;
                    *(__nv_bfloat162*)(Clo + (size_t)(m + 8) * KP + n) = lp1;
                }
            }
        }
    }
}

// ---------------- row softmax (in place), row length MM ------------------------
__global__ void softmax_rows(float* __restrict__ S)
{
    const int row = blockIdx.x;
    const int t = threadIdx.x;
    float* r = S + (size_t)row * MM;
    float v[8];
    #pragma unroll
    for (int i = 0; i < 8; ++i) v[i] = r[i * 256 + t];

    float mx = v[0];
    #pragma unroll
    for (int i = 1; i < 8; ++i) mx = fmaxf(mx, v[i]);

    __shared__ float sh[32];
    #pragma unroll
    for (int o = 16; o > 0; o >>= 1) mx = fmaxf(mx, __shfl_xor_sync(0xffffffff, mx, o));
    if ((t & 31) == 0) sh[t >> 5] = mx;
    __syncthreads();
    if (t < 32) {
        float m = (t < 8) ? sh[t] : -INFINITY;
        #pragma unroll
        for (int o = 4; o > 0; o >>= 1) m = fmaxf(m, __shfl_xor_sync(0xffffffff, m, o));
        sh[0] = m;
    }
    __syncthreads();
    mx = sh[0];
    __syncthreads();

    float sum = 0.f;
    #pragma unroll
    for (int i = 0; i < 8; ++i) { v[i] = expf(v[i] - mx); sum += v[i]; }
    #pragma unroll
    for (int o = 16; o > 0; o >>= 1) sum += __shfl_xor_sync(0xffffffff, sum, o);
    if ((t & 31) == 0) sh[t >> 5] = sum;
    __syncthreads();
    if (t < 32) {
        float s = (t < 8) ? sh[t] : 0.f;
        #pragma unroll
        for (int o = 4; o > 0; o >>= 1) s += __shfl_xor_sync(0xffffffff, s, o);
        sh[0] = s;
    }
    __syncthreads();
    float inv = 1.f / sh[0];
    #pragma unroll
    for (int i = 0; i < 8; ++i) r[i * 256 + t] = v[i] * inv;
}

// ---------------- column sums of P ----------------
__global__ void colsum_part(const float* __restrict__ P)
{
    int j = blockIdx.x * 256 + threadIdx.x;
    int r0 = blockIdx.y * 128;
    float acc = 0.f;
    for (int r = 0; r < 128; ++r) acc += P[(size_t)(r0 + r) * MM + j];
    g_cs_part[blockIdx.y * MM + j] = acc;
}

__global__ void colsum_reduce()
{
    int j = blockIdx.x * 256 + threadIdx.x;
    float acc = 0.f;
    #pragma unroll
    for (int c = 0; c < 16; ++c) acc += g_cs_part[c * MM + j];
    g_colsum[j] = acc;
}

// ---------------- u = (colsum @ inp) / M ----------------
__global__ void u_part(const float* __restrict__ X)
{
    int j = blockIdx.x * 256 + threadIdx.x;
    if (j >= DD) return;
    int r0 = blockIdx.y * 128;
    float acc = 0.f;
    for (int r = 0; r < 128; ++r) {
        int l = r0 + r;
        acc += g_colsum[l] * X[(size_t)l * DD + j];
    }
    g_part[blockIdx.y * DD + j] = acc;
}

__global__ void u_reduce()
{
    int j = blockIdx.x * 256 + threadIdx.x;
    if (j >= DD) return;
    float acc = 0.f;
    #pragma unroll
    for (int c = 0; c < 16; ++c) acc += g_part[c * DD + j];
    g_u[j] = acc * (1.0f / (float)MM);
}

// ---------------- context = u @ Wv + bv ----------------
__global__ void ctx2_part(const float* __restrict__ Wv)
{
    int j = blockIdx.x * 256 + threadIdx.x;
    if (j >= DD) return;
    int i0 = blockIdx.y * 481;
    float acc = 0.f;
    for (int r = 0; r < 481; ++r) {
        int i = i0 + r;
        if (i < DD) acc += g_u[i] * Wv[(size_t)i * DD + j];
    }
    g_part[blockIdx.y * DD + j] = acc;
}

__global__ void ctx2_reduce(const float* __restrict__ bv)
{
    int j = blockIdx.x * 256 + threadIdx.x;
    if (j >= DD) return;
    float acc = 0.f;
    #pragma unroll
    for (int c = 0; c < 16; ++c) acc += g_part[c * DD + j];
    g_context[j] = acc + bv[j];
}

// ---------------- sweep 1: cols [DD, NN), rows i<DD ----------------
__global__ void sweep1_part(const float* __restrict__ mu, const float* __restrict__ sig,
                            const float* __restrict__ eps)
{
    int jj = blockIdx.x * 256 + threadIdx.x;
    if (jj >= HH + OO) return;
    int j = DD + jj;
    int i0 = blockIdx.y * 126;
    float acc = 0.f;
    for (int r = 0; r < 126; ++r) {
        int i = i0 + r;
        size_t off = (size_t)i * NN + j;
        acc += g_context[i] * (mu[off] + sig[off] * eps[off]);
    }
    g_s1_part[blockIdx.y * (HH + OO) + jj] = acc;
}

__global__ void sweep1_final(const float* __restrict__ bmu, const float* __restrict__ bsig,
                             const float* __restrict__ epsb)
{
    int jj = blockIdx.x * 256 + threadIdx.x;
    if (jj >= HH + OO) return;
    int j = DD + jj;
    float acc = 0.f;
    for (int c = 0; c < 61; ++c) acc += g_s1_part[c * (HH + OO) + jj];
    g_vals1[jj] = tanhf(acc + bmu[j] + bsig[j] * epsb[j]);
}

// ---------------- sweep 2: cols [DD+HH, NN), all rows ----------------
__global__ void sweep2_part(const float* __restrict__ mu, const float* __restrict__ sig,
                            const float* __restrict__ eps)
{
    const int t = threadIdx.x;
    const int col = t & 7;
    const int lane = t >> 3;
    const int i0 = blockIdx.x * 257;
    const int j = DD + HH + col;
    float acc = 0.f;
    for (int r = lane; r < 257; r += 32) {
        int i = i0 + r;
        if (i < NN) {
            float vi = (i < DD) ? g_context[i] : g_vals1[i - DD];
            size_t off = (size_t)i * NN + j;
            acc += vi * (mu[off] + sig[off] * eps[off]);
        }
    }
    __shared__ float sh[256];
    sh[t] = acc;
    __syncthreads();
    for (int s = 128; s >= 8; s >>= 1) {
        if (t < s) sh[t] += sh[t + s];
        __syncthreads();
    }
    if (t < 8) g_s2_part[blockIdx.x * 8 + t] = sh[t];
}

__global__ void final_out(const float* __restrict__ bmu, const float* __restrict__ bsig,
                          const float* __restrict__ epsb, float* __restrict__ out)
{
    int t = threadIdx.x;
    if (t < OO) {
        float acc = 0.f;
        #pragma unroll
        for (int b = 0; b < 32; ++b) acc += g_s2_part[b * 8 + t];
        int j = DD + HH + t;
        float v = tanhf(acc + bmu[j] + bsig[j] * epsb[j]);
        out[t] = 1.0f / (1.0f + expf(-v));
    }
}

// ---------------- launcher -------------------------------------------------------
extern "C" void kernel_launch(void* const* d_in, const int* in_sizes, int n_in,
                              void* d_out, int out_size)
{
    const float* inp  = (const float*)d_in[0];
    const float* Wq   = (const float*)d_in[1];
    const float* bq   = (const float*)d_in[2];
    const float* Wk   = (const float*)d_in[3];
    const float* bk   = (const float*)d_in[4];
    const float* Wv   = (const float*)d_in[5];
    const float* bv   = (const float*)d_in[6];
    const float* wmu  = (const float*)d_in[7];
    const float* wsig = (const float*)d_in[8];
    const float* bmu  = (const float*)d_in[9];
    const float* bsig = (const float*)d_in[10];
    const float* epsw = (const float*)d_in[11];
    const float* epsb = (const float*)d_in[12];
    float* out = (float*)d_out;

    __nv_bfloat16 *ihi, *ilo, *wtqhi, *wtqlo, *wtkhi, *wtklo;
    __nv_bfloat16 *qhi, *qlo, *khi, *klo;
    float *sc;
    cudaGetSymbolAddress((void**)&ihi,   g_ihi);
    cudaGetSymbolAddress((void**)&ilo,   g_ilo);
    cudaGetSymbolAddress((void**)&wtqhi, g_wtqhi);
    cudaGetSymbolAddress((void**)&wtqlo, g_wtqlo);
    cudaGetSymbolAddress((void**)&wtkhi, g_wtkhi);
    cudaGetSymbolAddress((void**)&wtklo, g_wtklo);
    cudaGetSymbolAddress((void**)&qhi,   g_qhi);
    cudaGetSymbolAddress((void**)&qlo,   g_qlo);
    cudaGetSymbolAddress((void**)&khi,   g_khi);
    cudaGetSymbolAddress((void**)&klo,   g_klo);
    cudaGetSymbolAddress((void**)&sc,    g_scores);

    cudaFuncSetAttribute(tc_gemm, cudaFuncAttributeMaxDynamicSharedMemorySize,
                         SMEM_GEMM);

    const dim3 split_grid((KP / 4 + 255) / 256, MM);
    const dim3 tr_grid(WROWS / 32, KP / 32);
    const dim3 qk_grid(2 * (WROWS / 128), MM / 128);   // 122 x 16 (q & k fused)
    const dim3 sc_grid(MM / 128, MM / 128);            // 16 x 16

    // input split to bf16 hi/lo
    split_pad<<<split_grid, 256>>>(inp, ihi, ilo, DD);

    // transpose+split both weight matrices
    transpose_split<<<tr_grid, 256>>>(Wq, wtqhi, wtqlo);
    transpose_split<<<tr_grid, 256>>>(Wk, wtkhi, wtklo);

    // q = inp @ Wq + bq  AND  k = inp @ Wk + bk  (one launch, bf16 hi/lo out)
    tc_gemm<<<qk_grid, 128, SMEM_GEMM>>>(ihi, ilo,
                                         wtqhi, wtqlo, wtkhi, wtklo,
                                         bq, bk, WROWS / 128, 1.f,
                                         nullptr, 0, qhi, qlo, khi, klo);

    // scores = q @ k^T / sqrt(D)  (fp32 out)
    tc_gemm<<<sc_grid, 128, SMEM_GEMM>>>(qhi, qlo,
                                         khi, klo, nullptr, nullptr,
                                         nullptr, nullptr, 1 << 20,
                                         rsqrtf((float)DD),
                                         sc, MM, nullptr, nullptr, nullptr, nullptr);

    softmax_rows<<<MM, 256>>>(sc);

    colsum_part<<<dim3(MM / 256, 16), 256>>>(sc);
    colsum_reduce<<<MM / 256, 256>>>();

    // context = ((colsum/M) @ inp) @ Wv + bv
    u_part<<<dim3((DD + 255) / 256, 16), 256>>>(inp);
    u_reduce<<<(DD + 255) / 256, 256>>>();
    ctx2_part<<<dim3((DD + 255) / 256, 16), 256>>>(Wv);
    ctx2_reduce<<<(DD + 255) / 256, 256>>>(bv);

    sweep1_part<<<dim3(3, 61), 256>>>(wmu, wsig, epsw);
    sweep1_final<<<3, 256>>>(bmu, bsig, epsb);

    sweep2_part<<<32, 256>>>(wmu, wsig, epsw);
    final_out<<<1, 32>>>(bmu, bsig, epsb, out);
}

// round 12
// speedup vs baseline: 2.8487x; 1.0618x over previous
#include <cuda_runtime.h>
#include <cuda_bf16.h>
#include <cstdint>
#include <math.h>

// ---------------- problem constants ----------------
#define MM 2048      // num_memories
#define DD 7686      // input size
#define HH 512
#define OO 8
#define NN 8206      // DD + HH + OO
#define KP 7744      // K padded to multiple of 32
#define WROWS 7808   // padded B rows for W^T (61 * 128)
#define BKC 32
#define KCHUNKS (KP / BKC)   // 242

// ---------------- small PTX helpers ----------------
__device__ __forceinline__ uint32_t smem_to_u32(const void* p) {
    uint32_t a;
    asm("{ .reg .u64 t; cvta.to.shared.u64 t, %1; cvt.u32.u64 %0, t; }"
        : "=r"(a) : "l"(p));
    return a;
}

__device__ __forceinline__ void cpa16(uint32_t s, const void* g) {
    asm volatile("cp.async.cg.shared.global [%0], [%1], 16;" :: "r"(s), "l"(g) : "memory");
}
#define CP_COMMIT() asm volatile("cp.async.commit_group;" ::: "memory")

__device__ __forceinline__ void ldsm4(uint32_t (&r)[4], uint32_t addr) {
    asm volatile("ldmatrix.sync.aligned.m8n8.x4.shared.b16 {%0,%1,%2,%3}, [%4];"
                 : "=r"(r[0]), "=r"(r[1]), "=r"(r[2]), "=r"(r[3]) : "r"(addr));
}

__device__ __forceinline__ void mma16816(float (&d)[4], const uint32_t (&a)[4],
                                         const uint32_t b0, const uint32_t b1) {
    asm volatile(
        "mma.sync.aligned.m16n8k16.row.col.f32.bf16.bf16.f32 "
        "{%0,%1,%2,%3}, {%4,%5,%6,%7}, {%8,%9}, {%0,%1,%2,%3};"
        : "+f"(d[0]), "+f"(d[1]), "+f"(d[2]), "+f"(d[3])
        : "r"(a[0]), "r"(a[1]), "r"(a[2]), "r"(a[3]), "r"(b0), "r"(b1));
}

// SW64 swizzle for 64B-wide smem rows (conflict-free ldmatrix)
__device__ __forceinline__ uint32_t sw_off(int row, int c) {
    uint32_t o = (uint32_t)(row * 64 + c * 16);
    return o ^ ((o >> 3) & 0x30);
}

// ---------------- device scratch ----------------
__device__ __nv_bfloat16 g_ihi[(size_t)MM * KP];
__device__ __nv_bfloat16 g_ilo[(size_t)MM * KP];
__device__ __nv_bfloat16 g_wtqhi[(size_t)WROWS * KP];
__device__ __nv_bfloat16 g_wtqlo[(size_t)WROWS * KP];
__device__ __nv_bfloat16 g_wtkhi[(size_t)WROWS * KP];
__device__ __nv_bfloat16 g_wtklo[(size_t)WROWS * KP];
__device__ __nv_bfloat16 g_qhi[(size_t)MM * KP];
__device__ __nv_bfloat16 g_qlo[(size_t)MM * KP];
__device__ __nv_bfloat16 g_khi[(size_t)MM * KP];
__device__ __nv_bfloat16 g_klo[(size_t)MM * KP];
__device__ float g_scores[(size_t)MM * MM];
__device__ float g_cs_part[16 * MM];
__device__ float g_colsum[MM];
__device__ float g_part[16 * DD];
__device__ float g_u[DD];
__device__ float g_context[DD];
__device__ float g_s1_part[61 * (HH + OO)];
__device__ float g_vals1[HH + OO];
__device__ float g_s2_part[32 * OO];

// ---------------- split fp32 -> bf16 hi/lo, pad cols to KP (8B stores) ----------
__global__ void split_pad(const float* __restrict__ x,
                          __nv_bfloat16* __restrict__ hi,
                          __nv_bfloat16* __restrict__ lo, int cols)
{
    int c = (blockIdx.x * 256 + threadIdx.x) * 4;
    if (c >= KP) return;
    int r = blockIdx.y;
    const float* xr = x + (size_t)r * cols;
    uint32_t hw[2], lw[2];
    #pragma unroll
    for (int j = 0; j < 2; ++j) {
        float v0 = (c + 2*j     < cols) ? xr[c + 2*j]     : 0.f;
        float v1 = (c + 2*j + 1 < cols) ? xr[c + 2*j + 1] : 0.f;
        __nv_bfloat16 h0 = __float2bfloat16(v0);
        __nv_bfloat16 h1 = __float2bfloat16(v1);
        __nv_bfloat162 hp; hp.x = h0; hp.y = h1;
        __nv_bfloat162 lp;
        lp.x = __float2bfloat16(v0 - __bfloat162float(h0));
        lp.y = __float2bfloat16(v1 - __bfloat162float(h1));
        hw[j] = *(uint32_t*)&hp;
        lw[j] = *(uint32_t*)&lp;
    }
    *(uint2*)(hi + (size_t)r * KP + c) = make_uint2(hw[0], hw[1]);
    *(uint2*)(lo + (size_t)r * KP + c) = make_uint2(lw[0], lw[1]);
}

// ---------------- transpose + split: W[k][n] -> Wt[n][k] bf16 hi/lo -------------
__global__ void transpose_split(const float* __restrict__ W,
                                __nv_bfloat16* __restrict__ Thi,
                                __nv_bfloat16* __restrict__ Tlo)
{
    __shared__ float s[32][33];
    const int t = threadIdx.x;
    const int n0 = blockIdx.x * 32;
    const int k0 = blockIdx.y * 32;

    #pragma unroll
    for (int i = 0; i < 4; ++i) {
        int idx = i * 256 + t;
        int kl = idx >> 5, nl = idx & 31;
        int k = k0 + kl, n = n0 + nl;
        s[kl][nl] = (k < DD && n < DD) ? W[(size_t)k * DD + n] : 0.f;
    }
    __syncthreads();

    const int a = t >> 3;          // n-local 0..31
    const int g = (t & 7) * 4;     // k-group
    uint32_t hw[2], lw[2];
    #pragma unroll
    for (int j = 0; j < 2; ++j) {
        float v0 = s[g + 2*j][a];
        float v1 = s[g + 2*j + 1][a];
        __nv_bfloat16 h0 = __float2bfloat16(v0);
        __nv_bfloat16 h1 = __float2bfloat16(v1);
        __nv_bfloat162 hp; hp.x = h0; hp.y = h1;
        __nv_bfloat162 lp;
        lp.x = __float2bfloat16(v0 - __bfloat162float(h0));
        lp.y = __float2bfloat16(v1 - __bfloat162float(h1));
        hw[j] = *(uint32_t*)&hp;
        lw[j] = *(uint32_t*)&lp;
    }
    size_t off = (size_t)(n0 + a) * KP + (k0 + g);
    *(uint2*)(Thi + off) = make_uint2(hw[0], hw[1]);
    *(uint2*)(Tlo + off) = make_uint2(lw[0], lw[1]);
}

// ---------------- bf16x3 mma.sync GEMM, CTA tile 128x128, 4 warps ---------------
// Dual-B dispatch (q & k fused). Term-major passes with fragment ldsm
// interleaved into the mma stream, and the NEXT-chunk cp.async issue deferred
// into pass-2/pass-3 slack (off the chunk-head critical path). Per-accumulator
// operation sequence unchanged => bit-identical results.
#define T_AHI 0
#define T_ALO 8192
#define T_BHI 16384
#define T_BLO 24576
#define STAGE_BYTES 32768
#define NSTAGE 3
#define SMEM_GEMM (NSTAGE * STAGE_BYTES)   // 98304

__global__ __launch_bounds__(128, 2)
void tc_gemm(const __nv_bfloat16* __restrict__ Ahi, const __nv_bfloat16* __restrict__ Alo,
             const __nv_bfloat16* __restrict__ B1hi, const __nv_bfloat16* __restrict__ B1lo,
             const __nv_bfloat16* __restrict__ B2hi, const __nv_bfloat16* __restrict__ B2lo,
             const float* __restrict__ bias1, const float* __restrict__ bias2,
             int nsplit, float scale,
             float* __restrict__ Cf, int Cld,
             __nv_bfloat16* __restrict__ C1hi, __nv_bfloat16* __restrict__ C1lo,
             __nv_bfloat16* __restrict__ C2hi, __nv_bfloat16* __restrict__ C2lo)
{
    extern __shared__ char smem[];
    const uint32_t sb = smem_to_u32(smem);
    const int t   = threadIdx.x;
    const int wid = t >> 5;
    const int lid = t & 31;
    const int m0 = blockIdx.y * 128;

    const __nv_bfloat16 *Bhi, *Blo;
    const float* bias;
    __nv_bfloat16 *Chi, *Clo;
    int n0;
    if ((int)blockIdx.x < nsplit) {
        n0 = blockIdx.x * 128;
        Bhi = B1hi; Blo = B1lo; bias = bias1; Chi = C1hi; Clo = C1lo;
    } else {
        n0 = (blockIdx.x - nsplit) * 128;
        Bhi = B2hi; Blo = B2lo; bias = bias2; Chi = C2hi; Clo = C2lo;
    }

    const int rl = t >> 2;
    const int cl = t & 3;
    const uint32_t soR[4] = { sw_off(rl, cl), sw_off(rl + 32, cl),
                              sw_off(rl + 64, cl), sw_off(rl + 96, cl) };

    float acc[4][8][4];
    #pragma unroll
    for (int a = 0; a < 4; ++a)
        #pragma unroll
        for (int b = 0; b < 8; ++b)
            #pragma unroll
            for (int c = 0; c < 4; ++c) acc[a][b][c] = 0.f;

    const char* pAhi = (const char*)Ahi;
    const char* pAlo = (const char*)Alo;
    const char* pBhi = (const char*)Bhi;
    const char* pBlo = (const char*)Blo;

    // full-burst loader (used only for the two priming stages)
    auto load_stage = [&](int kc, int slot) {
        const int k0 = kc * BKC;
        const uint32_t st = sb + slot * STAGE_BYTES;
        #pragma unroll
        for (int i = 0; i < 4; ++i) {
            const int r = rl + 32 * i;
            size_t ga = (((size_t)(m0 + r) * KP + k0 + cl * 8) << 1);
            size_t gb = (((size_t)(n0 + r) * KP + k0 + cl * 8) << 1);
            cpa16(st + T_AHI + soR[i], pAhi + ga);
            cpa16(st + T_ALO + soR[i], pAlo + ga);
            cpa16(st + T_BHI + soR[i], pBhi + gb);
            cpa16(st + T_BLO + soR[i], pBlo + gb);
        }
        CP_COMMIT();
    };

    const int wm = wid >> 1;       // 0..1 (m offset 64)
    const int wn = wid & 1;        // 0..1 (n offset 64)
    const int lrow = lid & 15;
    const int lcg  = lid >> 4;     // 0..1

    load_stage(0, 0);
    load_stage(1, 1);

    int slot = 0;                  // kc % 3
    int nslot = 2;                 // (kc+2) % 3
    for (int kc = 0; kc < KCHUNKS; ++kc) {
        asm volatile("cp.async.wait_group 1;" ::: "memory");
        __syncthreads();

        const bool pf = (kc + 2 < KCHUNKS);
        const int pk0 = (kc + 2) * BKC;
        const uint32_t pst = sb + nslot * STAGE_BYTES;
        const uint32_t st = sb + slot * STAGE_BYTES;
        slot = (slot == 2) ? 0 : slot + 1;
        nslot = (nslot == 2) ? 0 : nslot + 1;

        // deferred prefetch slice for chunk kc+2 (issued inside mma slack)
        auto load_slice = [&](int i) {
            if (pf) {
                const int r = rl + 32 * i;
                size_t ga = (((size_t)(m0 + r) * KP + pk0 + cl * 8) << 1);
                size_t gb = (((size_t)(n0 + r) * KP + pk0 + cl * 8) << 1);
                cpa16(pst + T_AHI + soR[i], pAhi + ga);
                cpa16(pst + T_ALO + soR[i], pAlo + ga);
                cpa16(pst + T_BHI + soR[i], pBhi + gb);
                cpa16(pst + T_BLO + soR[i], pBlo + gb);
            }
        };

        #pragma unroll
        for (int ks = 0; ks < 2; ++ks) {
            const int ccol = ks * 2 + lcg;
            uint32_t ahi[4][4], alo[4][4];
            uint32_t bhi[8][2], blo[8][2];

            // minimal preload: A-hi fragments + first B-hi pair
            #pragma unroll
            for (int mt = 0; mt < 4; ++mt)
                ldsm4(ahi[mt], st + T_AHI + sw_off(wm * 64 + mt * 16 + lrow, ccol));
            {
                uint32_t r[4];
                ldsm4(r, st + T_BHI + sw_off(wn * 64 + lrow, ccol));
                bhi[0][0] = r[0]; bhi[0][1] = r[2];
                bhi[1][0] = r[1]; bhi[1][1] = r[3];
            }

            // pass 1: hi*hi  (prefetch remaining bhi + all blo under mma)
            #pragma unroll
            for (int p = 0; p < 4; ++p) {
                if (p < 3) {
                    uint32_t r[4];
                    ldsm4(r, st + T_BHI + sw_off(wn * 64 + (p + 1) * 16 + lrow, ccol));
                    bhi[2*p+2][0] = r[0]; bhi[2*p+2][1] = r[2];
                    bhi[2*p+3][0] = r[1]; bhi[2*p+3][1] = r[3];
                }
                {
                    uint32_t r[4];
                    ldsm4(r, st + T_BLO + sw_off(wn * 64 + p * 16 + lrow, ccol));
                    blo[2*p][0] = r[0]; blo[2*p][1] = r[2];
                    blo[2*p+1][0] = r[1]; blo[2*p+1][1] = r[3];
                }
                #pragma unroll
                for (int mt = 0; mt < 4; ++mt) {
                    mma16816(acc[mt][2*p],     ahi[mt], bhi[2*p][0],   bhi[2*p][1]);
                    mma16816(acc[mt][2*p + 1], ahi[mt], bhi[2*p+1][0], bhi[2*p+1][1]);
                }
            }

            // pass 2: hi*lo  (prefetch alo under mma; inject cp.async slice)
            load_slice(ks * 2);
            #pragma unroll
            for (int p = 0; p < 4; ++p) {
                ldsm4(alo[p], st + T_ALO + sw_off(wm * 64 + p * 16 + lrow, ccol));
                #pragma unroll
                for (int mt = 0; mt < 4; ++mt) {
                    mma16816(acc[mt][2*p],     ahi[mt], blo[2*p][0],   blo[2*p][1]);
                    mma16816(acc[mt][2*p + 1], ahi[mt], blo[2*p+1][0], blo[2*p+1][1]);
                }
            }

            // pass 3: lo*hi  (pure mma; inject second cp.async slice)
            load_slice(ks * 2 + 1);
            #pragma unroll
            for (int mt = 0; mt < 4; ++mt)
                #pragma unroll
                for (int q = 0; q < 8; ++q)
                    mma16816(acc[mt][q], alo[mt], bhi[q][0], bhi[q][1]);
        }

        CP_COMMIT();   // one group per chunk (empty near the tail)
    }

    // ---- epilogue ----
    const int g  = lid >> 2;
    const int t4 = lid & 3;
    #pragma unroll
    for (int mt = 0; mt < 4; ++mt) {
        #pragma unroll
        for (int nt = 0; nt < 8; ++nt) {
            const int m = m0 + wm * 64 + mt * 16 + g;
            const int n = n0 + wn * 64 + nt * 8 + t4 * 2;
            float d0 = acc[mt][nt][0], d1 = acc[mt][nt][1];
            float d2 = acc[mt][nt][2], d3 = acc[mt][nt][3];
            if (Cf) {
                if (n + 1 < Cld) {
                    float2 v0 = make_float2(d0 * scale, d1 * scale);
                    float2 v1 = make_float2(d2 * scale, d3 * scale);
                    *(float2*)(Cf + (size_t)m * Cld + n) = v0;
                    *(float2*)(Cf + (size_t)(m + 8) * Cld + n) = v1;
                }
            } else {
                if (n < KP) {
                    float b0 = (n     < DD) ? bias[n]     : 0.f;
                    float b1 = (n + 1 < DD) ? bias[n + 1] : 0.f;
                    float v0 = (n     < DD) ? d0 + b0 : 0.f;
                    float v1 = (n + 1 < DD) ? d1 + b1 : 0.f;
                    float v2 = (n     < DD) ? d2 + b0 : 0.f;
                    float v3 = (n + 1 < DD) ? d3 + b1 : 0.f;
                    __nv_bfloat16 h0 = __float2bfloat16(v0);
                    __nv_bfloat16 h1 = __float2bfloat16(v1);
                    __nv_bfloat16 h2 = __float2bfloat16(v2);
                    __nv_bfloat16 h3 = __float2bfloat16(v3);
                    __nv_bfloat162 hp0; hp0.x = h0; hp0.y = h1;
                    __nv_bfloat162 hp1; hp1.x = h2; hp1.y = h3;
                    __nv_bfloat162 lp0;
                    lp0.x = __float2bfloat16(v0 - __bfloat162float(h0));
                    lp0.y = __float2bfloat16(v1 - __bfloat162float(h1));
                    __nv_bfloat162 lp1;
                    lp1.x = __float2bfloat16(v2 - __bfloat162float(h2));
                    lp1.y = __float2bfloat16(v3 - __bfloat162float(h3));
                    *(__nv_bfloat162*)(Chi + (size_t)m * KP + n) = hp0;
                    *(__nv_bfloat162*)(Chi + (size_t)(m + 8) * KP + n) = hp1;
                    *(__nv_bfloat162*)(Clo + (size_t)m * KP + n) = lp0;
                    *(__nv_bfloat162*)(Clo + (size_t)(m + 8) * KP + n) = lp1;
                }
            }
        }
    }
}

// ---------------- row softmax (in place), row length MM ------------------------
__global__ void softmax_rows(float* __restrict__ S)
{
    const int row = blockIdx.x;
    const int t = threadIdx.x;
    float* r = S + (size_t)row * MM;
    float v[8];
    #pragma unroll
    for (int i = 0; i < 8; ++i) v[i] = r[i * 256 + t];

    float mx = v[0];
    #pragma unroll
    for (int i = 1; i < 8; ++i) mx = fmaxf(mx, v[i]);

    __shared__ float sh[32];
    #pragma unroll
    for (int o = 16; o > 0; o >>= 1) mx = fmaxf(mx, __shfl_xor_sync(0xffffffff, mx, o));
    if ((t & 31) == 0) sh[t >> 5] = mx;
    __syncthreads();
    if (t < 32) {
        float m = (t < 8) ? sh[t] : -INFINITY;
        #pragma unroll
        for (int o = 4; o > 0; o >>= 1) m = fmaxf(m, __shfl_xor_sync(0xffffffff, m, o));
        sh[0] = m;
    }
    __syncthreads();
    mx = sh[0];
    __syncthreads();

    float sum = 0.f;
    #pragma unroll
    for (int i = 0; i < 8; ++i) { v[i] = expf(v[i] - mx); sum += v[i]; }
    #pragma unroll
    for (int o = 16; o > 0; o >>= 1) sum += __shfl_xor_sync(0xffffffff, sum, o);
    if ((t & 31) == 0) sh[t >> 5] = sum;
    __syncthreads();
    if (t < 32) {
        float s = (t < 8) ? sh[t] : 0.f;
        #pragma unroll
        for (int o = 4; o > 0; o >>= 1) s += __shfl_xor_sync(0xffffffff, s, o);
        sh[0] = s;
    }
    __syncthreads();
    float inv = 1.f / sh[0];
    #pragma unroll
    for (int i = 0; i < 8; ++i) r[i * 256 + t] = v[i] * inv;
}

// ---------------- column sums of P ----------------
__global__ void colsum_part(const float* __restrict__ P)
{
    int j = blockIdx.x * 256 + threadIdx.x;
    int r0 = blockIdx.y * 128;
    float acc = 0.f;
    for (int r = 0; r < 128; ++r) acc += P[(size_t)(r0 + r) * MM + j];
    g_cs_part[blockIdx.y * MM + j] = acc;
}

__global__ void colsum_reduce()
{
    int j = blockIdx.x * 256 + threadIdx.x;
    float acc = 0.f;
    #pragma unroll
    for (int c = 0; c < 16; ++c) acc += g_cs_part[c * MM + j];
    g_colsum[j] = acc;
}

// ---------------- u = (colsum @ inp) / M ----------------
__global__ void u_part(const float* __restrict__ X)
{
    int j = blockIdx.x * 256 + threadIdx.x;
    if (j >= DD) return;
    int r0 = blockIdx.y * 128;
    float acc = 0.f;
    for (int r = 0; r < 128; ++r) {
        int l = r0 + r;
        acc += g_colsum[l] * X[(size_t)l * DD + j];
    }
    g_part[blockIdx.y * DD + j] = acc;
}

__global__ void u_reduce()
{
    int j = blockIdx.x * 256 + threadIdx.x;
    if (j >= DD) return;
    float acc = 0.f;
    #pragma unroll
    for (int c = 0; c < 16; ++c) acc += g_part[c * DD + j];
    g_u[j] = acc * (1.0f / (float)MM);
}

// ---------------- context = u @ Wv + bv ----------------
__global__ void ctx2_part(const float* __restrict__ Wv)
{
    int j = blockIdx.x * 256 + threadIdx.x;
    if (j >= DD) return;
    int i0 = blockIdx.y * 481;
    float acc = 0.f;
    for (int r = 0; r < 481; ++r) {
        int i = i0 + r;
        if (i < DD) acc += g_u[i] * Wv[(size_t)i * DD + j];
    }
    g_part[blockIdx.y * DD + j] = acc;
}

__global__ void ctx2_reduce(const float* __restrict__ bv)
{
    int j = blockIdx.x * 256 + threadIdx.x;
    if (j >= DD) return;
    float acc = 0.f;
    #pragma unroll
    for (int c = 0; c < 16; ++c) acc += g_part[c * DD + j];
    g_context[j] = acc + bv[j];
}

// ---------------- sweep 1: cols [DD, NN), rows i<DD ----------------
__global__ void sweep1_part(const float* __restrict__ mu, const float* __restrict__ sig,
                            const float* __restrict__ eps)
{
    int jj = blockIdx.x * 256 + threadIdx.x;
    if (jj >= HH + OO) return;
    int j = DD + jj;
    int i0 = blockIdx.y * 126;
    float acc = 0.f;
    for (int r = 0; r < 126; ++r) {
        int i = i0 + r;
        size_t off = (size_t)i * NN + j;
        acc += g_context[i] * (mu[off] + sig[off] * eps[off]);
    }
    g_s1_part[blockIdx.y * (HH + OO) + jj] = acc;
}

__global__ void sweep1_final(const float* __restrict__ bmu, const float* __restrict__ bsig,
                             const float* __restrict__ epsb)
{
    int jj = blockIdx.x * 256 + threadIdx.x;
    if (jj >= HH + OO) return;
    int j = DD + jj;
    float acc = 0.f;
    for (int c = 0; c < 61; ++c) acc += g_s1_part[c * (HH + OO) + jj];
    g_vals1[jj] = tanhf(acc + bmu[j] + bsig[j] * epsb[j]);
}

// ---------------- sweep 2: cols [DD+HH, NN), all rows ----------------
__global__ void sweep2_part(const float* __restrict__ mu, const float* __restrict__ sig,
                            const float* __restrict__ eps)
{
    const int t = threadIdx.x;
    const int col = t & 7;
    const int lane = t >> 3;
    const int i0 = blockIdx.x * 257;
    const int j = DD + HH + col;
    float acc = 0.f;
    for (int r = lane; r < 257; r += 32) {
        int i = i0 + r;
        if (i < NN) {
            float vi = (i < DD) ? g_context[i] : g_vals1[i - DD];
            size_t off = (size_t)i * NN + j;
            acc += vi * (mu[off] + sig[off] * eps[off]);
        }
    }
    __shared__ float sh[256];
    sh[t] = acc;
    __syncthreads();
    for (int s = 128; s >= 8; s >>= 1) {
        if (t < s) sh[t] += sh[t + s];
        __syncthreads();
    }
    if (t < 8) g_s2_part[blockIdx.x * 8 + t] = sh[t];
}

__global__ void final_out(const float* __restrict__ bmu, const float* __restrict__ bsig,
                          const float* __restrict__ epsb, float* __restrict__ out)
{
    int t = threadIdx.x;
    if (t < OO) {
        float acc = 0.f;
        #pragma unroll
        for (int b = 0; b < 32; ++b) acc += g_s2_part[b * 8 + t];
        int j = DD + HH + t;
        float v = tanhf(acc + bmu[j] + bsig[j] * epsb[j]);
        out[t] = 1.0f / (1.0f + expf(-v));
    }
}

// ---------------- launcher -------------------------------------------------------
extern "C" void kernel_launch(void* const* d_in, const int* in_sizes, int n_in,
                              void* d_out, int out_size)
{
    const float* inp  = (const float*)d_in[0];
    const float* Wq   = (const float*)d_in[1];
    const float* bq   = (const float*)d_in[2];
    const float* Wk   = (const float*)d_in[3];
    const float* bk   = (const float*)d_in[4];
    const float* Wv   = (const float*)d_in[5];
    const float* bv   = (const float*)d_in[6];
    const float* wmu  = (const float*)d_in[7];
    const float* wsig = (const float*)d_in[8];
    const float* bmu  = (const float*)d_in[9];
    const float* bsig = (const float*)d_in[10];
    const float* epsw = (const float*)d_in[11];
    const float* epsb = (const float*)d_in[12];
    float* out = (float*)d_out;

    __nv_bfloat16 *ihi, *ilo, *wtqhi, *wtqlo, *wtkhi, *wtklo;
    __nv_bfloat16 *qhi, *qlo, *khi, *klo;
    float *sc;
    cudaGetSymbolAddress((void**)&ihi,   g_ihi);
    cudaGetSymbolAddress((void**)&ilo,   g_ilo);
    cudaGetSymbolAddress((void**)&wtqhi, g_wtqhi);
    cudaGetSymbolAddress((void**)&wtqlo, g_wtqlo);
    cudaGetSymbolAddress((void**)&wtkhi, g_wtkhi);
    cudaGetSymbolAddress((void**)&wtklo, g_wtklo);
    cudaGetSymbolAddress((void**)&qhi,   g_qhi);
    cudaGetSymbolAddress((void**)&qlo,   g_qlo);
    cudaGetSymbolAddress((void**)&khi,   g_khi);
    cudaGetSymbolAddress((void**)&klo,   g_klo);
    cudaGetSymbolAddress((void**)&sc,    g_scores);

    cudaFuncSetAttribute(tc_gemm, cudaFuncAttributeMaxDynamicSharedMemorySize,
                         SMEM_GEMM);

    const dim3 split_grid((KP / 4 + 255) / 256, MM);
    const dim3 tr_grid(WROWS / 32, KP / 32);
    const dim3 qk_grid(2 * (WROWS / 128), MM / 128);   // 122 x 16 (q & k fused)
    const dim3 sc_grid(MM / 128, MM / 128);            // 16 x 16

    // input split to bf16 hi/lo
    split_pad<<<split_grid, 256>>>(inp, ihi, ilo, DD);

    // transpose+split both weight matrices
    transpose_split<<<tr_grid, 256>>>(Wq, wtqhi, wtqlo);
    transpose_split<<<tr_grid, 256>>>(Wk, wtkhi, wtklo);

    // q = inp @ Wq + bq  AND  k = inp @ Wk + bk  (one launch, bf16 hi/lo out)
    tc_gemm<<<qk_grid, 128, SMEM_GEMM>>>(ihi, ilo,
                                         wtqhi, wtqlo, wtkhi, wtklo,
                                         bq, bk, WROWS / 128, 1.f,
                                         nullptr, 0, qhi, qlo, khi, klo);

    // scores = q @ k^T / sqrt(D)  (fp32 out)
    tc_gemm<<<sc_grid, 128, SMEM_GEMM>>>(qhi, qlo,
                                         khi, klo, nullptr, nullptr,
                                         nullptr, nullptr, 1 << 20,
                                         rsqrtf((float)DD),
                                         sc, MM, nullptr, nullptr, nullptr, nullptr);

    softmax_rows<<<MM, 256>>>(sc);

    colsum_part<<<dim3(MM / 256, 16), 256>>>(sc);
    colsum_reduce<<<MM / 256, 256>>>();

    // context = ((colsum/M) @ inp) @ Wv + bv
    u_part<<<dim3((DD + 255) / 256, 16), 256>>>(inp);
    u_reduce<<<(DD + 255) / 256, 256>>>();
    ctx2_part<<<dim3((DD + 255) / 256, 16), 256>>>(Wv);
    ctx2_reduce<<<(DD + 255) / 256, 256>>>(bv);

    sweep1_part<<<dim3(3, 61), 256>>>(wmu, wsig, epsw);
    sweep1_final<<<3, 256>>>(bmu, bsig, epsb);

    sweep2_part<<<32, 256>>>(wmu, wsig, epsw);
    final_out<<<1, 32>>>(bmu, bsig, epsb, out);
}